// round 2
// baseline (speedup 1.0000x reference)
#include <cuda_runtime.h>
#include <math.h>

#define NN   10000
#define EE   160000
#define ETOT 170000   // EE + NN self loops
#define FIN  128
#define HID  512
#define HH   8
#define CC   64
#define NCLS 10

// ---------------- scratch (device globals; no allocs allowed) ----------------
__device__ float g_h[NN * HID];
__device__ float g_xl[NN * HID];
__device__ float g_xr[NN * HID];
__device__ float g_out[NN * HID];
__device__ float g_ex[(size_t)ETOT * HH];
__device__ float g_denom[NN * HH];

// ---------------- generic 128x128x8 SGEMM, 256 thr, 8x8 per thread ----------
// A: [M,K] row-major, B: [K,N] row-major, C: [M,N]. bias over N. optional elu.
__global__ void sgemm128(const float* __restrict__ A, const float* __restrict__ B,
                         const float* __restrict__ bias, float* __restrict__ C,
                         int M, int N, int K, int doElu)
{
    __shared__ float As[8][128];
    __shared__ float Bs[8][128];

    const int tid = threadIdx.x;
    const int m0 = blockIdx.y * 128;
    const int n0 = blockIdx.x * 128;
    const int tx = tid & 15;
    const int ty = tid >> 4;

    float acc[8][8];
#pragma unroll
    for (int i = 0; i < 8; i++)
#pragma unroll
        for (int j = 0; j < 8; j++) acc[i][j] = 0.f;

    const int aRow  = tid >> 1;        // 0..127
    const int aCol4 = (tid & 1) * 4;   // 0 / 4
    const int bRow  = tid >> 5;        // 0..7
    const int bCol4 = (tid & 31) * 4;  // 0..124

    for (int k0 = 0; k0 < K; k0 += 8) {
        float4 av = make_float4(0.f, 0.f, 0.f, 0.f);
        if (m0 + aRow < M)
            av = *(const float4*)(A + (size_t)(m0 + aRow) * K + k0 + aCol4);
        As[aCol4 + 0][aRow] = av.x;
        As[aCol4 + 1][aRow] = av.y;
        As[aCol4 + 2][aRow] = av.z;
        As[aCol4 + 3][aRow] = av.w;

        float4 bv = *(const float4*)(B + (size_t)(k0 + bRow) * N + n0 + bCol4);
        *(float4*)&Bs[bRow][bCol4] = bv;

        __syncthreads();

#pragma unroll
        for (int k = 0; k < 8; k++) {
            float ra[8], rb[8];
            *(float4*)&ra[0] = *(const float4*)&As[k][ty * 8];
            *(float4*)&ra[4] = *(const float4*)&As[k][ty * 8 + 4];
            *(float4*)&rb[0] = *(const float4*)&Bs[k][tx * 8];
            *(float4*)&rb[4] = *(const float4*)&Bs[k][tx * 8 + 4];
#pragma unroll
            for (int i = 0; i < 8; i++)
#pragma unroll
                for (int j = 0; j < 8; j++) acc[i][j] += ra[i] * rb[j];
        }
        __syncthreads();
    }

#pragma unroll
    for (int i = 0; i < 8; i++) {
        int m = m0 + ty * 8 + i;
        if (m >= M) continue;
#pragma unroll
        for (int j = 0; j < 8; j += 4) {
            int n = n0 + tx * 8 + j;
            float4 v;
            v.x = acc[i][j + 0] + bias[n + 0];
            v.y = acc[i][j + 1] + bias[n + 1];
            v.z = acc[i][j + 2] + bias[n + 2];
            v.w = acc[i][j + 3] + bias[n + 3];
            if (doElu) {
                v.x = v.x > 0.f ? v.x : expm1f(v.x);
                v.y = v.y > 0.f ? v.y : expm1f(v.y);
                v.z = v.z > 0.f ? v.z : expm1f(v.z);
                v.w = v.w > 0.f ? v.w : expm1f(v.w);
            }
            *(float4*)(C + (size_t)m * N + n) = v;
        }
    }
}

// ---------------- zero helper ----------------
__global__ void zero_kernel(float* __restrict__ p, int n)
{
    int i = blockIdx.x * blockDim.x + threadIdx.x;
    if (i < n) p[i] = 0.f;
}

// ---------------- edge score pass: alpha -> ex = exp(alpha); denom scatter ---
// one warp per edge; each group of 4 lanes covers 16 channels of one head.
// NOTE: edge_index is int32 on device (JAX x64 disabled downgrades int64).
__global__ void edge_score(const int* __restrict__ ei,
                           const float* __restrict__ dist,
                           const float* __restrict__ We,
                           const float* __restrict__ att)
{
    __shared__ float4 sWe[HID / 4];
    __shared__ float4 sAtt[HID / 4];
    for (int i = threadIdx.x; i < HID / 4; i += blockDim.x) {
        sWe[i]  = ((const float4*)We)[i];
        sAtt[i] = ((const float4*)att)[i];
    }
    __syncthreads();

    const int e = blockIdx.x * (blockDim.x >> 5) + (threadIdx.x >> 5);
    const int lane = threadIdx.x & 31;
    if (e >= ETOT) return;

    int s, d; float dv;
    if (e < EE) { s = ei[e]; d = ei[EE + e]; dv = dist[e]; }
    else        { s = d = e - EE; dv = 0.f; }

    const float4* xls = (const float4*)(g_xl + (size_t)s * HID);
    const float4* xrd = (const float4*)(g_xr + (size_t)d * HID);

    float partial = 0.f;
#pragma unroll
    for (int q = 0; q < 4; q++) {
        int f4 = lane * 4 + q;
        float4 a = xls[f4];
        float4 b = xrd[f4];
        float4 w = sWe[f4];
        float4 t = sAtt[f4];
        float v;
        v = a.x + b.x + dv * w.x; v = v > 0.f ? v : 0.2f * v; partial += v * t.x;
        v = a.y + b.y + dv * w.y; v = v > 0.f ? v : 0.2f * v; partial += v * t.y;
        v = a.z + b.z + dv * w.z; v = v > 0.f ? v : 0.2f * v; partial += v * t.z;
        v = a.w + b.w + dv * w.w; v = v > 0.f ? v : 0.2f * v; partial += v * t.w;
    }
    partial += __shfl_xor_sync(0xffffffffu, partial, 1);
    partial += __shfl_xor_sync(0xffffffffu, partial, 2);
    if ((lane & 3) == 0) {
        int hh = lane >> 2;
        float ex = expf(partial);   // softmax shift-invariant; scores are O(1)
        g_ex[(size_t)e * HH + hh] = ex;
        atomicAdd(&g_denom[d * HH + hh], ex);
    }
}

// ---------------- edge aggregation pass: out[dst] += (ex/denom)*xl[src] -----
__global__ void edge_agg(const int* __restrict__ ei)
{
    const int e = blockIdx.x * (blockDim.x >> 5) + (threadIdx.x >> 5);
    const int lane = threadIdx.x & 31;
    if (e >= ETOT) return;

    int s, d;
    if (e < EE) { s = ei[e]; d = ei[EE + e]; }
    else        { s = d = e - EE; }

    const int hh = lane >> 2;
    const float w = g_ex[(size_t)e * HH + hh] / g_denom[d * HH + hh];

    const float4* xls = (const float4*)(g_xl + (size_t)s * HID);
    float* od = g_out + (size_t)d * HID;
#pragma unroll
    for (int q = 0; q < 4; q++) {
        int f4 = lane * 4 + q;
        float4 a = xls[f4];
        int base = f4 * 4;
        atomicAdd(od + base + 0, w * a.x);
        atomicAdd(od + base + 1, w * a.y);
        atomicAdd(od + base + 2, w * a.z);
        atomicAdd(od + base + 3, w * a.w);
    }
}

// ---------------- bias + elu : h = elu(out + bias_c) -------------------------
__global__ void bias_elu(const float* __restrict__ bias)
{
    int idx = blockIdx.x * blockDim.x + threadIdx.x;   // float4 index
    if (idx >= NN * (HID / 4)) return;
    int j = idx & (HID / 4 - 1);
    float4 v = ((const float4*)g_out)[idx];
    float4 b = ((const float4*)bias)[j];
    v.x += b.x; v.y += b.y; v.z += b.z; v.w += b.w;
    v.x = v.x > 0.f ? v.x : expm1f(v.x);
    v.y = v.y > 0.f ? v.y : expm1f(v.y);
    v.z = v.z > 0.f ? v.z : expm1f(v.z);
    v.w = v.w > 0.f ? v.w : expm1f(v.w);
    ((float4*)g_h)[idx] = v;
}

// ---------------- final: logits = h @ Wa + ba; log_softmax -------------------
__global__ void final_kernel(const float* __restrict__ Wa,
                             const float* __restrict__ ba,
                             float* __restrict__ out)
{
    const int row = blockIdx.x * (blockDim.x >> 5) + (threadIdx.x >> 5);
    const int lane = threadIdx.x & 31;
    if (row >= NN) return;

    const float* hrow = g_h + (size_t)row * HID;
    float acc[NCLS];
#pragma unroll
    for (int c = 0; c < NCLS; c++) acc[c] = 0.f;

    for (int k = lane; k < HID; k += 32) {
        float hv = hrow[k];
        const float* wrow = Wa + (size_t)k * NCLS;
#pragma unroll
        for (int c = 0; c < NCLS; c++) acc[c] += hv * wrow[c];
    }
#pragma unroll
    for (int off = 16; off > 0; off >>= 1)
#pragma unroll
        for (int c = 0; c < NCLS; c++)
            acc[c] += __shfl_xor_sync(0xffffffffu, acc[c], off);

    if (lane == 0) {
        float z[NCLS], mx = -1e30f;
#pragma unroll
        for (int c = 0; c < NCLS; c++) { z[c] = acc[c] + ba[c]; mx = fmaxf(mx, z[c]); }
        float s = 0.f;
#pragma unroll
        for (int c = 0; c < NCLS; c++) s += expf(z[c] - mx);
        float lse = mx + logf(s);
#pragma unroll
        for (int c = 0; c < NCLS; c++) out[(size_t)row * NCLS + c] = z[c] - lse;
    }
}

// ---------------- launch ----------------
extern "C" void kernel_launch(void* const* d_in, const int* in_sizes, int n_in,
                              void* d_out, int out_size)
{
    const float* x    = (const float*)d_in[0];
    const int*   ei   = (const int*)d_in[1];      // int32! (JAX x64 disabled)
    const float* dist = (const float*)d_in[2];
    const float* Wb   = (const float*)d_in[3];
    const float* bb   = (const float*)d_in[4];
    const float* Wl   = (const float*)d_in[5];
    const float* bl   = (const float*)d_in[6];
    const float* Wr   = (const float*)d_in[7];
    const float* br   = (const float*)d_in[8];
    const float* We   = (const float*)d_in[9];
    const float* att  = (const float*)d_in[10];
    const float* bc   = (const float*)d_in[11];
    const float* Wa   = (const float*)d_in[12];
    const float* ba   = (const float*)d_in[13];
    float* out = (float*)d_out;

    float *ph, *pxl, *pxr, *pout, *pden;
    cudaGetSymbolAddress((void**)&ph,   g_h);
    cudaGetSymbolAddress((void**)&pxl,  g_xl);
    cudaGetSymbolAddress((void**)&pxr,  g_xr);
    cudaGetSymbolAddress((void**)&pout, g_out);
    cudaGetSymbolAddress((void**)&pden, g_denom);

    dim3 gg(HID / 128, (NN + 127) / 128);   // 4 x 79

    // fcnn_before: h = elu(x @ Wb + bb)
    sgemm128<<<gg, 256>>>(x, Wb, bb, ph, NN, HID, FIN, 1);

    const int edgeBlocks = (ETOT + 7) / 8;  // warp per edge, 8 warps/block

    for (int i = 0; i < 3; i++) {
        sgemm128<<<gg, 256>>>(ph, Wl + (size_t)i * HID * HID, bl + i * HID, pxl,
                              NN, HID, HID, 0);
        sgemm128<<<gg, 256>>>(ph, Wr + (size_t)i * HID * HID, br + i * HID, pxr,
                              NN, HID, HID, 0);
        zero_kernel<<<(NN * HH + 255) / 256, 256>>>(pden, NN * HH);
        zero_kernel<<<(NN * HID + 255) / 256, 256>>>(pout, NN * HID);
        edge_score<<<edgeBlocks, 256>>>(ei, dist, We + (size_t)i * HID,
                                        att + (size_t)i * HID);
        edge_agg<<<edgeBlocks, 256>>>(ei);
        // elu after every conv (layers 0,1 inter-layer; layer 2 via fcnn_after)
        bias_elu<<<(NN * (HID / 4) + 255) / 256, 256>>>(bc + (size_t)i * HID);
    }

    final_kernel<<<(NN + 7) / 8, 256>>>(Wa, ba, out);
}

// round 4
// speedup vs baseline: 1.3633x; 1.3633x over previous
#include <cuda_runtime.h>
#include <math.h>
#include <stdint.h>

#define NN   10000
#define EE   160000
#define ETOT 170000   // EE + NN self loops
#define FIN  128
#define HID  512
#define HH   8
#define CC   64
#define NCLS 10

// ---------------- scratch (device globals; no allocs allowed) ----------------
__device__ float g_h[NN * HID];
__device__ float g_xl[NN * HID];
__device__ float g_xr[NN * HID];
__device__ float g_out[NN * HID];
__device__ float g_ex[(size_t)ETOT * HH];
__device__ float g_denom[NN * HH];

// ---------------- tf32 helpers ----------------
__device__ __forceinline__ uint32_t f2tf32(float f)
{
    uint32_t r;
    asm("cvt.rna.tf32.f32 %0, %1;" : "=r"(r) : "f"(f));
    return r;
}

__device__ __forceinline__ void mma_tf32(float* c, const uint32_t* a, const uint32_t* b)
{
    asm volatile(
        "mma.sync.aligned.m16n8k8.row.col.f32.tf32.tf32.f32 "
        "{%0,%1,%2,%3}, {%4,%5,%6,%7}, {%8,%9}, {%0,%1,%2,%3};"
        : "+f"(c[0]), "+f"(c[1]), "+f"(c[2]), "+f"(c[3])
        : "r"(a[0]), "r"(a[1]), "r"(a[2]), "r"(a[3]), "r"(b[0]), "r"(b[1]));
}

// ---------------- TF32 tensor-core GEMM: 128x128 tile, 256 thr, K-chunk 16 --
// A: [M,K] row-major, B: [K,N] row-major, C=[M,N] + bias, optional elu.
// warp grid 2(m)x4(n); each warp 64x32 via 4x4 m16n8k8 mmas.
__global__ void __launch_bounds__(256, 1)
tf32gemm(const float* __restrict__ A, const float* __restrict__ B,
         const float* __restrict__ bias, float* __restrict__ C,
         int M, int N, int K, int doElu)
{
    __shared__ float As[16][132];   // [k][m], padded (132 mod 32 = 4)
    __shared__ float Bs[16][132];   // [k][n], padded

    const int tid  = threadIdx.x;
    const int wid  = tid >> 5;
    const int lane = tid & 31;
    const int g    = lane >> 2;   // groupID 0..7
    const int tg   = lane & 3;    // threadInGroup 0..3

    const int m0 = blockIdx.y * 128;
    const int n0 = blockIdx.x * 128;
    const int warpM = (wid >> 2) * 64;
    const int warpN = (wid & 3) * 32;

    float acc[4][4][4];
#pragma unroll
    for (int mt = 0; mt < 4; mt++)
#pragma unroll
        for (int nt = 0; nt < 4; nt++)
#pragma unroll
            for (int i = 0; i < 4; i++) acc[mt][nt][i] = 0.f;

    for (int k0 = 0; k0 < K; k0 += 16) {
        // load A tile 128x16 (transposed into As[k][m]); 2 float4 per thread
#pragma unroll
        for (int i = 0; i < 2; i++) {
            int idx = tid + i * 256;
            int row = idx >> 2;             // 0..127
            int c4  = (idx & 3) * 4;        // 0,4,8,12
            float4 v = make_float4(0.f, 0.f, 0.f, 0.f);
            if (m0 + row < M)
                v = *(const float4*)(A + (size_t)(m0 + row) * K + k0 + c4);
            As[c4 + 0][row] = v.x;
            As[c4 + 1][row] = v.y;
            As[c4 + 2][row] = v.z;
            As[c4 + 3][row] = v.w;
        }
        // load B tile 16x128; 2 float4 per thread (conflict-free)
#pragma unroll
        for (int i = 0; i < 2; i++) {
            int idx = tid + i * 256;
            int kr = idx >> 5;              // 0..15
            int c4 = (idx & 31) * 4;        // 0..124
            float4 v = *(const float4*)(B + (size_t)(k0 + kr) * N + n0 + c4);
            *(float4*)&Bs[kr][c4] = v;
        }
        __syncthreads();

#pragma unroll
        for (int kk = 0; kk < 16; kk += 8) {
            uint32_t a[4][4], b[4][2];
#pragma unroll
            for (int mt = 0; mt < 4; mt++) {
                int mr = warpM + mt * 16 + g;
                a[mt][0] = f2tf32(As[kk + tg][mr]);
                a[mt][1] = f2tf32(As[kk + tg][mr + 8]);
                a[mt][2] = f2tf32(As[kk + tg + 4][mr]);
                a[mt][3] = f2tf32(As[kk + tg + 4][mr + 8]);
            }
#pragma unroll
            for (int nt = 0; nt < 4; nt++) {
                int nc = warpN + nt * 8 + g;
                b[nt][0] = f2tf32(Bs[kk + tg][nc]);
                b[nt][1] = f2tf32(Bs[kk + tg + 4][nc]);
            }
#pragma unroll
            for (int mt = 0; mt < 4; mt++)
#pragma unroll
                for (int nt = 0; nt < 4; nt++)
                    mma_tf32(acc[mt][nt], a[mt], b[nt]);
        }
        __syncthreads();
    }

    // epilogue: C[row][col..col+1] pairs; bias + optional elu
#pragma unroll
    for (int mt = 0; mt < 4; mt++) {
        int row0 = m0 + warpM + mt * 16 + g;
        int row1 = row0 + 8;
#pragma unroll
        for (int nt = 0; nt < 4; nt++) {
            int col = n0 + warpN + nt * 8 + tg * 2;
            float bx = bias[col], by = bias[col + 1];
            float v0 = acc[mt][nt][0] + bx;
            float v1 = acc[mt][nt][1] + by;
            float v2 = acc[mt][nt][2] + bx;
            float v3 = acc[mt][nt][3] + by;
            if (doElu) {
                v0 = v0 > 0.f ? v0 : expm1f(v0);
                v1 = v1 > 0.f ? v1 : expm1f(v1);
                v2 = v2 > 0.f ? v2 : expm1f(v2);
                v3 = v3 > 0.f ? v3 : expm1f(v3);
            }
            if (row0 < M) *(float2*)(C + (size_t)row0 * N + col) = make_float2(v0, v1);
            if (row1 < M) *(float2*)(C + (size_t)row1 * N + col) = make_float2(v2, v3);
        }
    }
}

// ---------------- zero helper (both scratch arrays in one launch) -----------
__global__ void zero2_kernel(float* __restrict__ p1, int n1,
                             float* __restrict__ p2, int n2)
{
    int i = blockIdx.x * blockDim.x + threadIdx.x;
    if (i < n1) p1[i] = 0.f;
    if (i < n2) p2[i] = 0.f;
}

// ---------------- edge score pass: ex = exp(alpha); denom scatter -----------
// one warp per edge; each group of 4 lanes covers 16 channels of one head.
// NOTE: edge_index is int32 on device (JAX x64 disabled downgrades int64).
__global__ void edge_score(const int* __restrict__ ei,
                           const float* __restrict__ dist,
                           const float* __restrict__ We,
                           const float* __restrict__ att)
{
    __shared__ float4 sWe[HID / 4];
    __shared__ float4 sAtt[HID / 4];
    for (int i = threadIdx.x; i < HID / 4; i += blockDim.x) {
        sWe[i]  = ((const float4*)We)[i];
        sAtt[i] = ((const float4*)att)[i];
    }
    __syncthreads();

    const int e = blockIdx.x * (blockDim.x >> 5) + (threadIdx.x >> 5);
    const int lane = threadIdx.x & 31;
    if (e >= ETOT) return;

    int s, d; float dv;
    if (e < EE) { s = ei[e]; d = ei[EE + e]; dv = dist[e]; }
    else        { s = d = e - EE; dv = 0.f; }

    const float4* xls = (const float4*)(g_xl + (size_t)s * HID);
    const float4* xrd = (const float4*)(g_xr + (size_t)d * HID);

    float partial = 0.f;
#pragma unroll
    for (int q = 0; q < 4; q++) {
        int f4 = lane * 4 + q;
        float4 a = xls[f4];
        float4 b = xrd[f4];
        float4 w = sWe[f4];
        float4 t = sAtt[f4];
        float v;
        v = a.x + b.x + dv * w.x; v = v > 0.f ? v : 0.2f * v; partial += v * t.x;
        v = a.y + b.y + dv * w.y; v = v > 0.f ? v : 0.2f * v; partial += v * t.y;
        v = a.z + b.z + dv * w.z; v = v > 0.f ? v : 0.2f * v; partial += v * t.z;
        v = a.w + b.w + dv * w.w; v = v > 0.f ? v : 0.2f * v; partial += v * t.w;
    }
    partial += __shfl_xor_sync(0xffffffffu, partial, 1);
    partial += __shfl_xor_sync(0xffffffffu, partial, 2);
    if ((lane & 3) == 0) {
        int hh = lane >> 2;
        float ex = expf(partial);   // softmax shift-invariant; scores are O(1)
        g_ex[(size_t)e * HH + hh] = ex;
        atomicAdd(&g_denom[d * HH + hh], ex);
    }
}

// ---------------- edge aggregation: out[dst] += (ex/denom)*xl[src] ----------
__global__ void edge_agg(const int* __restrict__ ei)
{
    const int e = blockIdx.x * (blockDim.x >> 5) + (threadIdx.x >> 5);
    const int lane = threadIdx.x & 31;
    if (e >= ETOT) return;

    int s, d;
    if (e < EE) { s = ei[e]; d = ei[EE + e]; }
    else        { s = d = e - EE; }

    const int hh = lane >> 2;
    const float w = g_ex[(size_t)e * HH + hh] / g_denom[d * HH + hh];

    const float4* xls = (const float4*)(g_xl + (size_t)s * HID);
    float* od = g_out + (size_t)d * HID;
#pragma unroll
    for (int q = 0; q < 4; q++) {
        int f4 = lane * 4 + q;
        float4 a = xls[f4];
        int base = f4 * 4;
        atomicAdd(od + base + 0, w * a.x);
        atomicAdd(od + base + 1, w * a.y);
        atomicAdd(od + base + 2, w * a.z);
        atomicAdd(od + base + 3, w * a.w);
    }
}

// ---------------- bias + elu : h = elu(out + bias_c) -------------------------
__global__ void bias_elu(const float* __restrict__ bias)
{
    int idx = blockIdx.x * blockDim.x + threadIdx.x;   // float4 index
    if (idx >= NN * (HID / 4)) return;
    int j = idx & (HID / 4 - 1);
    float4 v = ((const float4*)g_out)[idx];
    float4 b = ((const float4*)bias)[j];
    v.x += b.x; v.y += b.y; v.z += b.z; v.w += b.w;
    v.x = v.x > 0.f ? v.x : expm1f(v.x);
    v.y = v.y > 0.f ? v.y : expm1f(v.y);
    v.z = v.z > 0.f ? v.z : expm1f(v.z);
    v.w = v.w > 0.f ? v.w : expm1f(v.w);
    ((float4*)g_h)[idx] = v;
}

// ---------------- final: logits = h @ Wa + ba; log_softmax -------------------
__global__ void final_kernel(const float* __restrict__ Wa,
                             const float* __restrict__ ba,
                             float* __restrict__ out)
{
    const int row = blockIdx.x * (blockDim.x >> 5) + (threadIdx.x >> 5);
    const int lane = threadIdx.x & 31;
    if (row >= NN) return;

    const float* hrow = g_h + (size_t)row * HID;
    float acc[NCLS];
#pragma unroll
    for (int c = 0; c < NCLS; c++) acc[c] = 0.f;

    for (int k = lane; k < HID; k += 32) {
        float hv = hrow[k];
        const float* wrow = Wa + (size_t)k * NCLS;
#pragma unroll
        for (int c = 0; c < NCLS; c++) acc[c] += hv * wrow[c];
    }
#pragma unroll
    for (int off = 16; off > 0; off >>= 1)
#pragma unroll
        for (int c = 0; c < NCLS; c++)
            acc[c] += __shfl_xor_sync(0xffffffffu, acc[c], off);

    if (lane == 0) {
        float z[NCLS], mx = -1e30f;
#pragma unroll
        for (int c = 0; c < NCLS; c++) { z[c] = acc[c] + ba[c]; mx = fmaxf(mx, z[c]); }
        float s = 0.f;
#pragma unroll
        for (int c = 0; c < NCLS; c++) s += expf(z[c] - mx);
        float lse = mx + logf(s);
#pragma unroll
        for (int c = 0; c < NCLS; c++) out[(size_t)row * NCLS + c] = z[c] - lse;
    }
}

// ---------------- launch ----------------
extern "C" void kernel_launch(void* const* d_in, const int* in_sizes, int n_in,
                              void* d_out, int out_size)
{
    const float* x    = (const float*)d_in[0];
    const int*   ei   = (const int*)d_in[1];      // int32! (JAX x64 disabled)
    const float* dist = (const float*)d_in[2];
    const float* Wb   = (const float*)d_in[3];
    const float* bb   = (const float*)d_in[4];
    const float* Wl   = (const float*)d_in[5];
    const float* bl   = (const float*)d_in[6];
    const float* Wr   = (const float*)d_in[7];
    const float* br   = (const float*)d_in[8];
    const float* We   = (const float*)d_in[9];
    const float* att  = (const float*)d_in[10];
    const float* bc   = (const float*)d_in[11];
    const float* Wa   = (const float*)d_in[12];
    const float* ba   = (const float*)d_in[13];
    float* out = (float*)d_out;

    float *ph, *pxl, *pxr, *pout, *pden;
    cudaGetSymbolAddress((void**)&ph,   g_h);
    cudaGetSymbolAddress((void**)&pxl,  g_xl);
    cudaGetSymbolAddress((void**)&pxr,  g_xr);
    cudaGetSymbolAddress((void**)&pout, g_out);
    cudaGetSymbolAddress((void**)&pden, g_denom);

    dim3 gg(HID / 128, (NN + 127) / 128);   // 4 x 79

    // fcnn_before: h = elu(x @ Wb + bb)
    tf32gemm<<<gg, 256>>>(x, Wb, bb, ph, NN, HID, FIN, 1);

    const int edgeBlocks = (ETOT + 7) / 8;  // warp per edge, 8 warps/block

    for (int i = 0; i < 3; i++) {
        tf32gemm<<<gg, 256>>>(ph, Wl + (size_t)i * HID * HID, bl + i * HID, pxl,
                              NN, HID, HID, 0);
        tf32gemm<<<gg, 256>>>(ph, Wr + (size_t)i * HID * HID, br + i * HID, pxr,
                              NN, HID, HID, 0);
        zero2_kernel<<<(NN * HID + 255) / 256, 256>>>(pout, NN * HID, pden, NN * HH);
        edge_score<<<edgeBlocks, 256>>>(ei, dist, We + (size_t)i * HID,
                                        att + (size_t)i * HID);
        edge_agg<<<edgeBlocks, 256>>>(ei);
        // elu after every conv (layers 0,1 inter-layer; layer 2 via fcnn_after)
        bias_elu<<<(NN * (HID / 4) + 255) / 256, 256>>>(bc + (size_t)i * HID);
    }

    final_kernel<<<(NN + 7) / 8, 256>>>(Wa, ba, out);
}

// round 6
// speedup vs baseline: 3.1798x; 2.3324x over previous
#include <cuda_runtime.h>
#include <cuda_bf16.h>
#include <math.h>
#include <stdint.h>

typedef __nv_bfloat16 bf16;

#define NN   10000
#define EE   160000
#define ETOT 170000   // EE + NN self loops
#define FIN  128
#define HID  512
#define HH   8
#define CC   64
#define NCLS 10

// ---------------- scratch (device globals; no allocs allowed) ----------------
__device__ float g_h [NN * HID];          // fp32 h (for final layer)
__device__ bf16  g_hb[NN * HID];          // bf16 h (GEMM A input)
__device__ bf16  g_xb[NN * FIN];          // bf16 x
__device__ float g_xl[NN * HID];
__device__ float g_xr[NN * HID];
__device__ float g_ex[(size_t)ETOT * HH];
__device__ float g_denom[NN * HH];
__device__ bf16  g_wbT[HID * FIN];        // Wb^T  [n][k]
__device__ bf16  g_wlT[3 * HID * HID];    // Wl^T per layer
__device__ bf16  g_wrT[3 * HID * HID];    // Wr^T per layer
__device__ int   g_cnt[NN];
__device__ int   g_offs[NN + 1];
__device__ int   g_cursor[NN];
__device__ int   g_csrc[ETOT];
__device__ int   g_ceid[ETOT];

// ---------------- small helpers ----------------
__global__ void zero_f(float* __restrict__ p, int n)
{
    int i = blockIdx.x * blockDim.x + threadIdx.x;
    if (i < n) p[i] = 0.f;
}
__global__ void zero_i(int* __restrict__ p, int n)
{
    int i = blockIdx.x * blockDim.x + threadIdx.x;
    if (i < n) p[i] = 0;
}
__global__ void copy_i(const int* __restrict__ a, int* __restrict__ b, int n)
{
    int i = blockIdx.x * blockDim.x + threadIdx.x;
    if (i < n) b[i] = a[i];
}
__global__ void conv_x_kernel(const float* __restrict__ x)
{
    int i = blockIdx.x * blockDim.x + threadIdx.x;
    if (i < NN * FIN) g_xb[i] = __float2bfloat16(x[i]);
}

// transpose+convert: dst[n][k] = bf16(src[k][n]); K,N multiples of 32
__global__ void transp_bf16(const float* __restrict__ src, bf16* __restrict__ dst,
                            int K, int N)
{
    __shared__ float tile[32][33];
    int k0 = blockIdx.y * 32, n0 = blockIdx.x * 32;
    int tx = threadIdx.x, ty = threadIdx.y;   // 32 x 8
#pragma unroll
    for (int i = 0; i < 32; i += 8)
        tile[ty + i][tx] = src[(size_t)(k0 + ty + i) * N + n0 + tx];
    __syncthreads();
#pragma unroll
    for (int i = 0; i < 32; i += 8)
        dst[(size_t)(n0 + ty + i) * K + k0 + tx] = __float2bfloat16(tile[tx][ty + i]);
}

// ---------------- CSR build ----------------
__global__ void hist_kernel(const int* __restrict__ ei)
{
    int e = blockIdx.x * blockDim.x + threadIdx.x;
    if (e >= ETOT) return;
    int d = (e < EE) ? ei[EE + e] : e - EE;
    atomicAdd(&g_cnt[d], 1);
}

__global__ void scan_kernel()   // 1 block, 1024 threads; exclusive scan of g_cnt
{
    __shared__ int warpsum[32];
    __shared__ int carry;
    if (threadIdx.x == 0) carry = 0;
    __syncthreads();
    int lane = threadIdx.x & 31, wid = threadIdx.x >> 5;
    for (int base = 0; base < NN; base += 1024) {
        int i = base + threadIdx.x;
        int v = (i < NN) ? g_cnt[i] : 0;
        int x = v;
#pragma unroll
        for (int o = 1; o < 32; o <<= 1) {
            int y = __shfl_up_sync(0xffffffffu, x, o);
            if (lane >= o) x += y;
        }
        if (lane == 31) warpsum[wid] = x;
        __syncthreads();
        if (wid == 0) {
            int s = warpsum[lane];
#pragma unroll
            for (int o = 1; o < 32; o <<= 1) {
                int y = __shfl_up_sync(0xffffffffu, s, o);
                if (lane >= o) s += y;
            }
            warpsum[lane] = s;
        }
        __syncthreads();
        int pre = (wid > 0) ? warpsum[wid - 1] : 0;
        int incl = x + pre + carry;
        if (i < NN) g_offs[i] = incl - v;
        __syncthreads();
        if (threadIdx.x == 1023) carry = incl;
        __syncthreads();
    }
    if (threadIdx.x == 0) g_offs[NN] = carry;
}

__global__ void scatter_kernel(const int* __restrict__ ei)
{
    int e = blockIdx.x * blockDim.x + threadIdx.x;
    if (e >= ETOT) return;
    int s, d;
    if (e < EE) { s = ei[e]; d = ei[EE + e]; }
    else        { s = d = e - EE; }
    int pos = atomicAdd(&g_cursor[d], 1);
    g_csrc[pos] = s;
    g_ceid[pos] = e;
}

// ---------------- bf16 tensor-core GEMM -------------------------------------
// C[M,N] = A[M,K] @ B^T where B stored [N][K] bf16 (weights pre-transposed).
// 128x128 tile, 256 thr, K-chunk 32, cp.async double-buffered.
// If B1 != null: dual-output (blockIdx.x selects B0/C0 or B1/C1).
// outBf16: write bf16 to Cb instead of fp32 to C0.
__device__ __forceinline__ void mma_bf16(float* c, const uint32_t* a, const uint32_t* b)
{
    asm volatile(
        "mma.sync.aligned.m16n8k16.row.col.f32.bf16.bf16.f32 "
        "{%0,%1,%2,%3}, {%4,%5,%6,%7}, {%8,%9}, {%0,%1,%2,%3};"
        : "+f"(c[0]), "+f"(c[1]), "+f"(c[2]), "+f"(c[3])
        : "r"(a[0]), "r"(a[1]), "r"(a[2]), "r"(a[3]), "r"(b[0]), "r"(b[1]));
}
__device__ __forceinline__ void cp16(uint32_t dst, const void* src)
{
    asm volatile("cp.async.cg.shared.global [%0], [%1], 16;" :: "r"(dst), "l"(src));
}

#define STAGE_BYTES 20480   // A: 128*80, B: 128*80

__global__ void __launch_bounds__(256, 1)
bf16gemm(const bf16* __restrict__ A,
         const bf16* __restrict__ B0, const bf16* __restrict__ B1,
         const float* __restrict__ bias0, const float* __restrict__ bias1,
         float* __restrict__ C0, float* __restrict__ C1, bf16* __restrict__ Cb,
         int M, int K, int doElu)
{
    __shared__ __align__(16) unsigned char smem[2 * STAGE_BYTES];
    const int N = HID;

    const int tid  = threadIdx.x;
    const int wid  = tid >> 5;
    const int lane = tid & 31;
    const int g    = lane >> 2;
    const int tg   = lane & 3;

    const bf16* B = B0;
    float* C = C0;
    const float* bi = bias0;
    int bx = blockIdx.x;
    if (B1 != nullptr && bx >= ((int)gridDim.x >> 1)) {
        B = B1; C = C1; bi = bias1; bx -= (int)gridDim.x >> 1;
    }
    const int m0 = blockIdx.y * 128;
    const int n0 = bx * 128;
    const int warpM = (wid >> 2) * 64;
    const int warpN = (wid & 3) * 32;

    const uint32_t sbase = (uint32_t)__cvta_generic_to_shared(smem);

    // per-thread load indices (row, 16B quad)
    const int lrow = tid >> 2;          // row for i=0 (0..63); i adds 64
    const int lq   = tid & 3;

    float acc[4][4][4];
#pragma unroll
    for (int mt = 0; mt < 4; mt++)
#pragma unroll
        for (int nt = 0; nt < 4; nt++)
#pragma unroll
            for (int i = 0; i < 4; i++) acc[mt][nt][i] = 0.f;

    const int nStages = K >> 5;

    // issue loads for stage (k0) into buffer buf
    auto issue = [&](int buf, int k0) {
        uint32_t sA = sbase + buf * STAGE_BYTES;
        uint32_t sB = sA + 10240;
#pragma unroll
        for (int i = 0; i < 2; i++) {
            int row = lrow + i * 64;
            int ar = m0 + row; if (ar >= M) ar = M - 1;
            cp16(sA + row * 80 + lq * 16, A + (size_t)ar * K + k0 + lq * 8);
            cp16(sB + row * 80 + lq * 16, B + (size_t)(n0 + row) * K + k0 + lq * 8);
        }
        asm volatile("cp.async.commit_group;");
    };

    issue(0, 0);

    for (int ks = 0; ks < nStages; ks++) {
        if (ks + 1 < nStages) {
            issue((ks + 1) & 1, (ks + 1) << 5);
            asm volatile("cp.async.wait_group 1;");
        } else {
            asm volatile("cp.async.wait_group 0;");
        }
        __syncthreads();

        const uint32_t* As32 = (const uint32_t*)(smem + (ks & 1) * STAGE_BYTES);
        const uint32_t* Bs32 = (const uint32_t*)(smem + (ks & 1) * STAGE_BYTES + 10240);

#pragma unroll
        for (int kk = 0; kk < 32; kk += 16) {
            const int j0 = kk >> 1;     // uint32 index base
            uint32_t a[4][4], b[4][2];
#pragma unroll
            for (int mt = 0; mt < 4; mt++) {
                int mr = warpM + mt * 16 + g;
                a[mt][0] = As32[mr * 20 + j0 + tg];
                a[mt][1] = As32[(mr + 8) * 20 + j0 + tg];
                a[mt][2] = As32[mr * 20 + j0 + tg + 4];
                a[mt][3] = As32[(mr + 8) * 20 + j0 + tg + 4];
            }
#pragma unroll
            for (int nt = 0; nt < 4; nt++) {
                int nc = warpN + nt * 8 + g;
                b[nt][0] = Bs32[nc * 20 + j0 + tg];
                b[nt][1] = Bs32[nc * 20 + j0 + tg + 4];
            }
#pragma unroll
            for (int mt = 0; mt < 4; mt++)
#pragma unroll
                for (int nt = 0; nt < 4; nt++)
                    mma_bf16(acc[mt][nt], a[mt], b[nt]);
        }
        __syncthreads();
    }

    // epilogue
#pragma unroll
    for (int mt = 0; mt < 4; mt++) {
        int row0 = m0 + warpM + mt * 16 + g;
        int row1 = row0 + 8;
#pragma unroll
        for (int nt = 0; nt < 4; nt++) {
            int col = n0 + warpN + nt * 8 + tg * 2;
            float bx0 = bi[col], bx1 = bi[col + 1];
            float v0 = acc[mt][nt][0] + bx0;
            float v1 = acc[mt][nt][1] + bx1;
            float v2 = acc[mt][nt][2] + bx0;
            float v3 = acc[mt][nt][3] + bx1;
            if (doElu) {
                v0 = v0 > 0.f ? v0 : expm1f(v0);
                v1 = v1 > 0.f ? v1 : expm1f(v1);
                v2 = v2 > 0.f ? v2 : expm1f(v2);
                v3 = v3 > 0.f ? v3 : expm1f(v3);
            }
            if (Cb != nullptr) {
                if (row0 < M)
                    *(__nv_bfloat162*)(Cb + (size_t)row0 * N + col) =
                        __nv_bfloat162(__float2bfloat16(v0), __float2bfloat16(v1));
                if (row1 < M)
                    *(__nv_bfloat162*)(Cb + (size_t)row1 * N + col) =
                        __nv_bfloat162(__float2bfloat16(v2), __float2bfloat16(v3));
            } else {
                if (row0 < M) *(float2*)(C + (size_t)row0 * N + col) = make_float2(v0, v1);
                if (row1 < M) *(float2*)(C + (size_t)row1 * N + col) = make_float2(v2, v3);
            }
        }
    }
}

// ---------------- edge score pass: ex = exp(alpha); denom scatter -----------
__global__ void edge_score(const int* __restrict__ ei,
                           const float* __restrict__ dist,
                           const float* __restrict__ We,
                           const float* __restrict__ att)
{
    __shared__ float4 sWe[HID / 4];
    __shared__ float4 sAtt[HID / 4];
    for (int i = threadIdx.x; i < HID / 4; i += blockDim.x) {
        sWe[i]  = ((const float4*)We)[i];
        sAtt[i] = ((const float4*)att)[i];
    }
    __syncthreads();

    const int e = blockIdx.x * (blockDim.x >> 5) + (threadIdx.x >> 5);
    const int lane = threadIdx.x & 31;
    if (e >= ETOT) return;

    int s, d; float dv;
    if (e < EE) { s = ei[e]; d = ei[EE + e]; dv = dist[e]; }
    else        { s = d = e - EE; dv = 0.f; }

    const float4* xls = (const float4*)(g_xl + (size_t)s * HID);
    const float4* xrd = (const float4*)(g_xr + (size_t)d * HID);

    float partial = 0.f;
#pragma unroll
    for (int q = 0; q < 4; q++) {
        int f4 = lane * 4 + q;
        float4 a = xls[f4];
        float4 b = xrd[f4];
        float4 w = sWe[f4];
        float4 t = sAtt[f4];
        float v;
        v = a.x + b.x + dv * w.x; v = v > 0.f ? v : 0.2f * v; partial += v * t.x;
        v = a.y + b.y + dv * w.y; v = v > 0.f ? v : 0.2f * v; partial += v * t.y;
        v = a.z + b.z + dv * w.z; v = v > 0.f ? v : 0.2f * v; partial += v * t.z;
        v = a.w + b.w + dv * w.w; v = v > 0.f ? v : 0.2f * v; partial += v * t.w;
    }
    partial += __shfl_xor_sync(0xffffffffu, partial, 1);
    partial += __shfl_xor_sync(0xffffffffu, partial, 2);
    if ((lane & 3) == 0) {
        int hh = lane >> 2;
        float ex = expf(partial);   // softmax shift-invariant; scores are O(1)
        g_ex[(size_t)e * HH + hh] = ex;
        atomicAdd(&g_denom[d * HH + hh], ex);
    }
}

// ---------------- node gather: h[d] = elu(bias + sum_e w_e * xl[src_e]) ----
// warp per node; lane owns 16 consecutive channels (head = lane>>2).
__global__ void node_gather(const float* __restrict__ bias)
{
    const int node = blockIdx.x * (blockDim.x >> 5) + (threadIdx.x >> 5);
    const int lane = threadIdx.x & 31;
    if (node >= NN) return;

    const int head = lane >> 2;
    const float inv = 1.f / g_denom[node * HH + head];   // self-loop => denom>0
    const int st = g_offs[node], en = g_offs[node + 1];

    float4 acc0 = make_float4(0.f, 0.f, 0.f, 0.f);
    float4 acc1 = acc0, acc2 = acc0, acc3 = acc0;

    for (int j = st; j < en; j++) {
        int s = g_csrc[j];
        int e = g_ceid[j];
        float w = g_ex[(size_t)e * HH + head] * inv;
        const float4* xs = (const float4*)(g_xl + (size_t)s * HID) + lane * 4;
        float4 a0 = xs[0], a1 = xs[1], a2 = xs[2], a3 = xs[3];
        acc0.x += w * a0.x; acc0.y += w * a0.y; acc0.z += w * a0.z; acc0.w += w * a0.w;
        acc1.x += w * a1.x; acc1.y += w * a1.y; acc1.z += w * a1.z; acc1.w += w * a1.w;
        acc2.x += w * a2.x; acc2.y += w * a2.y; acc2.z += w * a2.z; acc2.w += w * a2.w;
        acc3.x += w * a3.x; acc3.y += w * a3.y; acc3.z += w * a3.z; acc3.w += w * a3.w;
    }

    const float4* b4 = (const float4*)bias + lane * 4;
    float4 accs[4] = {acc0, acc1, acc2, acc3};
    float* hp = g_h + (size_t)node * HID + lane * 16;
    bf16* hbp = g_hb + (size_t)node * HID + lane * 16;
#pragma unroll
    for (int q = 0; q < 4; q++) {
        float4 b = b4[q];
        float4 v = accs[q];
        v.x += b.x; v.y += b.y; v.z += b.z; v.w += b.w;
        v.x = v.x > 0.f ? v.x : expm1f(v.x);
        v.y = v.y > 0.f ? v.y : expm1f(v.y);
        v.z = v.z > 0.f ? v.z : expm1f(v.z);
        v.w = v.w > 0.f ? v.w : expm1f(v.w);
        *(float4*)(hp + q * 4) = v;
        __nv_bfloat162 p0(__float2bfloat16(v.x), __float2bfloat16(v.y));
        __nv_bfloat162 p1(__float2bfloat16(v.z), __float2bfloat16(v.w));
        *(__nv_bfloat162*)(hbp + q * 4)     = p0;
        *(__nv_bfloat162*)(hbp + q * 4 + 2) = p1;
    }
}

// ---------------- final: logits = h @ Wa + ba; log_softmax -------------------
__global__ void final_kernel(const float* __restrict__ Wa,
                             const float* __restrict__ ba,
                             float* __restrict__ out)
{
    const int row = blockIdx.x * (blockDim.x >> 5) + (threadIdx.x >> 5);
    const int lane = threadIdx.x & 31;
    if (row >= NN) return;

    const float* hrow = g_h + (size_t)row * HID;
    float acc[NCLS];
#pragma unroll
    for (int c = 0; c < NCLS; c++) acc[c] = 0.f;

    for (int k = lane; k < HID; k += 32) {
        float hv = hrow[k];
        const float* wrow = Wa + (size_t)k * NCLS;
#pragma unroll
        for (int c = 0; c < NCLS; c++) acc[c] += hv * wrow[c];
    }
#pragma unroll
    for (int off = 16; off > 0; off >>= 1)
#pragma unroll
        for (int c = 0; c < NCLS; c++)
            acc[c] += __shfl_xor_sync(0xffffffffu, acc[c], off);

    if (lane == 0) {
        float z[NCLS], mx = -1e30f;
#pragma unroll
        for (int c = 0; c < NCLS; c++) { z[c] = acc[c] + ba[c]; mx = fmaxf(mx, z[c]); }
        float s = 0.f;
#pragma unroll
        for (int c = 0; c < NCLS; c++) s += expf(z[c] - mx);
        float lse = mx + logf(s);
#pragma unroll
        for (int c = 0; c < NCLS; c++) out[(size_t)row * NCLS + c] = z[c] - lse;
    }
}

// ---------------- launch ----------------
extern "C" void kernel_launch(void* const* d_in, const int* in_sizes, int n_in,
                              void* d_out, int out_size)
{
    const float* x    = (const float*)d_in[0];
    const int*   ei   = (const int*)d_in[1];      // int32 (JAX x64 disabled)
    const float* dist = (const float*)d_in[2];
    const float* Wb   = (const float*)d_in[3];
    const float* bb   = (const float*)d_in[4];
    const float* Wl   = (const float*)d_in[5];
    const float* bl   = (const float*)d_in[6];
    const float* Wr   = (const float*)d_in[7];
    const float* br   = (const float*)d_in[8];
    const float* We   = (const float*)d_in[9];
    const float* att  = (const float*)d_in[10];
    const float* bc   = (const float*)d_in[11];
    const float* Wa   = (const float*)d_in[12];
    const float* ba   = (const float*)d_in[13];
    float* out = (float*)d_out;

    float *pxl, *pxr, *pden;
    bf16 *phb, *pxb, *pwbT, *pwlT, *pwrT;
    int *pcnt, *poffs, *pcur;
    cudaGetSymbolAddress((void**)&pxl,  g_xl);
    cudaGetSymbolAddress((void**)&pxr,  g_xr);
    cudaGetSymbolAddress((void**)&pden, g_denom);
    cudaGetSymbolAddress((void**)&phb,  g_hb);
    cudaGetSymbolAddress((void**)&pxb,  g_xb);
    cudaGetSymbolAddress((void**)&pwbT, g_wbT);
    cudaGetSymbolAddress((void**)&pwlT, g_wlT);
    cudaGetSymbolAddress((void**)&pwrT, g_wrT);
    cudaGetSymbolAddress((void**)&pcnt, g_cnt);
    cudaGetSymbolAddress((void**)&poffs, g_offs);
    cudaGetSymbolAddress((void**)&pcur, g_cursor);

    // ---- prep: conversions + transposes + CSR ----
    conv_x_kernel<<<(NN * FIN + 255) / 256, 256>>>(x);
    dim3 tb(32, 8);
    transp_bf16<<<dim3(HID / 32, FIN / 32), tb>>>(Wb, pwbT, FIN, HID);
    for (int i = 0; i < 3; i++) {
        transp_bf16<<<dim3(HID / 32, HID / 32), tb>>>(Wl + (size_t)i * HID * HID,
                                                      pwlT + (size_t)i * HID * HID, HID, HID);
        transp_bf16<<<dim3(HID / 32, HID / 32), tb>>>(Wr + (size_t)i * HID * HID,
                                                      pwrT + (size_t)i * HID * HID, HID, HID);
    }
    zero_i<<<(NN + 255) / 256, 256>>>(pcnt, NN);
    hist_kernel<<<(ETOT + 255) / 256, 256>>>(ei);
    scan_kernel<<<1, 1024>>>();
    copy_i<<<(NN + 255) / 256, 256>>>(poffs, pcur, NN);
    scatter_kernel<<<(ETOT + 255) / 256, 256>>>(ei);

    // ---- fcnn_before: hb = bf16(elu(x @ Wb + bb)) ----
    bf16gemm<<<dim3(HID / 128, (NN + 127) / 128), 256>>>(
        pxb, pwbT, nullptr, bb, nullptr, nullptr, nullptr, phb, NN, FIN, 1);

    const int edgeBlocks = (ETOT + 7) / 8;

    for (int i = 0; i < 3; i++) {
        // fused dual GEMM: xl = hb @ Wl^T + bl ; xr = hb @ Wr^T + br (fp32 out)
        bf16gemm<<<dim3(2 * HID / 128, (NN + 127) / 128), 256>>>(
            phb, pwlT + (size_t)i * HID * HID, pwrT + (size_t)i * HID * HID,
            bl + i * HID, br + i * HID, pxl, pxr, nullptr, NN, HID, 0);
        zero_f<<<(NN * HH + 255) / 256, 256>>>(pden, NN * HH);
        edge_score<<<edgeBlocks, 256>>>(ei, dist, We + (size_t)i * HID,
                                        att + (size_t)i * HID);
        node_gather<<<(NN + 7) / 8, 256>>>(bc + (size_t)i * HID);
    }

    final_kernel<<<(NN + 7) / 8, 256>>>(Wa, ba, out);
}

// round 7
// speedup vs baseline: 5.0207x; 1.5789x over previous
#include <cuda_runtime.h>
#include <cuda_bf16.h>
#include <math.h>
#include <stdint.h>

typedef __nv_bfloat16 bf16;

#define NN   10000
#define EE   160000
#define ETOT 170000   // EE + NN self loops
#define FIN  128
#define HID  512
#define HH   8
#define CC   64
#define NCLS 10
#define MAXDEG 64     // smem fast path; exact recompute fallback beyond

// ---------------- scratch (device globals; no allocs allowed) ----------------
__device__ float g_h [NN * HID];          // fp32 h (for final layer)
__device__ bf16  g_hb[NN * HID];          // bf16 h (GEMM A input)
__device__ bf16  g_xb[NN * FIN];          // bf16 x
__device__ float g_xl[NN * HID];
__device__ float g_xr[NN * HID];
__device__ bf16  g_wbT[HID * FIN];        // Wb^T  [n][k]
__device__ bf16  g_wlT[3 * HID * HID];    // Wl^T per layer
__device__ bf16  g_wrT[3 * HID * HID];    // Wr^T per layer
__device__ int   g_cnt[NN];
__device__ int   g_offs[NN + 1];
__device__ int   g_cursor[NN];
__device__ int   g_csrc[ETOT];
__device__ float g_cdist[ETOT];

// ---------------- small helpers ----------------
__global__ void zero_i(int* __restrict__ p, int n)
{
    int i = blockIdx.x * blockDim.x + threadIdx.x;
    if (i < n) p[i] = 0;
}
__global__ void copy_i(const int* __restrict__ a, int* __restrict__ b, int n)
{
    int i = blockIdx.x * blockDim.x + threadIdx.x;
    if (i < n) b[i] = a[i];
}
__global__ void conv_x_kernel(const float* __restrict__ x)
{
    int i = blockIdx.x * blockDim.x + threadIdx.x;
    if (i < NN * FIN) g_xb[i] = __float2bfloat16(x[i]);
}

// transpose+convert: dst[n][k] = bf16(src[k][n]); K,N multiples of 32
__global__ void transp_bf16(const float* __restrict__ src, bf16* __restrict__ dst,
                            int K, int N)
{
    __shared__ float tile[32][33];
    int k0 = blockIdx.y * 32, n0 = blockIdx.x * 32;
    int tx = threadIdx.x, ty = threadIdx.y;   // 32 x 8
#pragma unroll
    for (int i = 0; i < 32; i += 8)
        tile[ty + i][tx] = src[(size_t)(k0 + ty + i) * N + n0 + tx];
    __syncthreads();
#pragma unroll
    for (int i = 0; i < 32; i += 8)
        dst[(size_t)(n0 + ty + i) * K + k0 + tx] = __float2bfloat16(tile[tx][ty + i]);
}

// batched version for the six HID x HID weight matrices (Wl 0..2, Wr 0..2)
__global__ void transp_bf16_batch6(const float* __restrict__ Wl,
                                   const float* __restrict__ Wr)
{
    __shared__ float tile[32][33];
    int z = blockIdx.z;
    const float* src = (z < 3) ? Wl + (size_t)z * HID * HID
                               : Wr + (size_t)(z - 3) * HID * HID;
    bf16* dst = (z < 3) ? g_wlT + (size_t)z * HID * HID
                        : g_wrT + (size_t)(z - 3) * HID * HID;
    int k0 = blockIdx.y * 32, n0 = blockIdx.x * 32;
    int tx = threadIdx.x, ty = threadIdx.y;
#pragma unroll
    for (int i = 0; i < 32; i += 8)
        tile[ty + i][tx] = src[(size_t)(k0 + ty + i) * HID + n0 + tx];
    __syncthreads();
#pragma unroll
    for (int i = 0; i < 32; i += 8)
        dst[(size_t)(n0 + ty + i) * HID + k0 + tx] = __float2bfloat16(tile[tx][ty + i]);
}

// ---------------- CSR build ----------------
__global__ void hist_kernel(const int* __restrict__ ei)
{
    int e = blockIdx.x * blockDim.x + threadIdx.x;
    if (e >= ETOT) return;
    int d = (e < EE) ? ei[EE + e] : e - EE;
    atomicAdd(&g_cnt[d], 1);
}

__global__ void scan_kernel()   // 1 block, 1024 threads; exclusive scan of g_cnt
{
    __shared__ int warpsum[32];
    __shared__ int carry;
    if (threadIdx.x == 0) carry = 0;
    __syncthreads();
    int lane = threadIdx.x & 31, wid = threadIdx.x >> 5;
    for (int base = 0; base < NN; base += 1024) {
        int i = base + threadIdx.x;
        int v = (i < NN) ? g_cnt[i] : 0;
        int x = v;
#pragma unroll
        for (int o = 1; o < 32; o <<= 1) {
            int y = __shfl_up_sync(0xffffffffu, x, o);
            if (lane >= o) x += y;
        }
        if (lane == 31) warpsum[wid] = x;
        __syncthreads();
        if (wid == 0) {
            int s = warpsum[lane];
#pragma unroll
            for (int o = 1; o < 32; o <<= 1) {
                int y = __shfl_up_sync(0xffffffffu, s, o);
                if (lane >= o) s += y;
            }
            warpsum[lane] = s;
        }
        __syncthreads();
        int pre = (wid > 0) ? warpsum[wid - 1] : 0;
        int incl = x + pre + carry;
        if (i < NN) g_offs[i] = incl - v;
        __syncthreads();
        if (threadIdx.x == 1023) carry = incl;
        __syncthreads();
    }
    if (threadIdx.x == 0) g_offs[NN] = carry;
}

__global__ void scatter_kernel(const int* __restrict__ ei,
                               const float* __restrict__ dist)
{
    int e = blockIdx.x * blockDim.x + threadIdx.x;
    if (e >= ETOT) return;
    int s, d; float dv;
    if (e < EE) { s = ei[e]; d = ei[EE + e]; dv = dist[e]; }
    else        { s = d = e - EE; dv = 0.f; }
    int pos = atomicAdd(&g_cursor[d], 1);
    g_csrc[pos] = s;
    g_cdist[pos] = dv;
}

// ---------------- bf16 tensor-core GEMM -------------------------------------
__device__ __forceinline__ void mma_bf16(float* c, const uint32_t* a, const uint32_t* b)
{
    asm volatile(
        "mma.sync.aligned.m16n8k16.row.col.f32.bf16.bf16.f32 "
        "{%0,%1,%2,%3}, {%4,%5,%6,%7}, {%8,%9}, {%0,%1,%2,%3};"
        : "+f"(c[0]), "+f"(c[1]), "+f"(c[2]), "+f"(c[3])
        : "r"(a[0]), "r"(a[1]), "r"(a[2]), "r"(a[3]), "r"(b[0]), "r"(b[1]));
}
__device__ __forceinline__ void cp16(uint32_t dst, const void* src)
{
    asm volatile("cp.async.cg.shared.global [%0], [%1], 16;" :: "r"(dst), "l"(src));
}

#define STAGE_BYTES 20480   // A: 128*80, B: 128*80

__global__ void __launch_bounds__(256, 2)
bf16gemm(const bf16* __restrict__ A,
         const bf16* __restrict__ B0, const bf16* __restrict__ B1,
         const float* __restrict__ bias0, const float* __restrict__ bias1,
         float* __restrict__ C0, float* __restrict__ C1, bf16* __restrict__ Cb,
         int M, int K, int doElu)
{
    __shared__ __align__(16) unsigned char smem[2 * STAGE_BYTES];
    const int N = HID;

    const int tid  = threadIdx.x;
    const int wid  = tid >> 5;
    const int lane = tid & 31;
    const int g    = lane >> 2;
    const int tg   = lane & 3;

    const bf16* B = B0;
    float* C = C0;
    const float* bi = bias0;
    int bx = blockIdx.x;
    if (B1 != nullptr && bx >= ((int)gridDim.x >> 1)) {
        B = B1; C = C1; bi = bias1; bx -= (int)gridDim.x >> 1;
    }
    const int m0 = blockIdx.y * 128;
    const int n0 = bx * 128;
    const int warpM = (wid >> 2) * 64;
    const int warpN = (wid & 3) * 32;

    const uint32_t sbase = (uint32_t)__cvta_generic_to_shared(smem);

    const int lrow = tid >> 2;          // row for i=0 (0..63); i adds 64
    const int lq   = tid & 3;

    float acc[4][4][4];
#pragma unroll
    for (int mt = 0; mt < 4; mt++)
#pragma unroll
        for (int nt = 0; nt < 4; nt++)
#pragma unroll
            for (int i = 0; i < 4; i++) acc[mt][nt][i] = 0.f;

    const int nStages = K >> 5;

    auto issue = [&](int buf, int k0) {
        uint32_t sA = sbase + buf * STAGE_BYTES;
        uint32_t sB = sA + 10240;
#pragma unroll
        for (int i = 0; i < 2; i++) {
            int row = lrow + i * 64;
            int ar = m0 + row; if (ar >= M) ar = M - 1;
            cp16(sA + row * 80 + lq * 16, A + (size_t)ar * K + k0 + lq * 8);
            cp16(sB + row * 80 + lq * 16, B + (size_t)(n0 + row) * K + k0 + lq * 8);
        }
        asm volatile("cp.async.commit_group;");
    };

    issue(0, 0);

    for (int ks = 0; ks < nStages; ks++) {
        if (ks + 1 < nStages) {
            issue((ks + 1) & 1, (ks + 1) << 5);
            asm volatile("cp.async.wait_group 1;");
        } else {
            asm volatile("cp.async.wait_group 0;");
        }
        __syncthreads();

        const uint32_t* As32 = (const uint32_t*)(smem + (ks & 1) * STAGE_BYTES);
        const uint32_t* Bs32 = (const uint32_t*)(smem + (ks & 1) * STAGE_BYTES + 10240);

#pragma unroll
        for (int kk = 0; kk < 32; kk += 16) {
            const int j0 = kk >> 1;
            uint32_t a[4][4], b[4][2];
#pragma unroll
            for (int mt = 0; mt < 4; mt++) {
                int mr = warpM + mt * 16 + g;
                a[mt][0] = As32[mr * 20 + j0 + tg];
                a[mt][1] = As32[(mr + 8) * 20 + j0 + tg];
                a[mt][2] = As32[mr * 20 + j0 + tg + 4];
                a[mt][3] = As32[(mr + 8) * 20 + j0 + tg + 4];
            }
#pragma unroll
            for (int nt = 0; nt < 4; nt++) {
                int nc = warpN + nt * 8 + g;
                b[nt][0] = Bs32[nc * 20 + j0 + tg];
                b[nt][1] = Bs32[nc * 20 + j0 + tg + 4];
            }
#pragma unroll
            for (int mt = 0; mt < 4; mt++)
#pragma unroll
                for (int nt = 0; nt < 4; nt++)
                    mma_bf16(acc[mt][nt], a[mt], b[nt]);
        }
        __syncthreads();
    }

#pragma unroll
    for (int mt = 0; mt < 4; mt++) {
        int row0 = m0 + warpM + mt * 16 + g;
        int row1 = row0 + 8;
#pragma unroll
        for (int nt = 0; nt < 4; nt++) {
            int col = n0 + warpN + nt * 8 + tg * 2;
            float bx0 = bi[col], bx1 = bi[col + 1];
            float v0 = acc[mt][nt][0] + bx0;
            float v1 = acc[mt][nt][1] + bx1;
            float v2 = acc[mt][nt][2] + bx0;
            float v3 = acc[mt][nt][3] + bx1;
            if (doElu) {
                v0 = v0 > 0.f ? v0 : expm1f(v0);
                v1 = v1 > 0.f ? v1 : expm1f(v1);
                v2 = v2 > 0.f ? v2 : expm1f(v2);
                v3 = v3 > 0.f ? v3 : expm1f(v3);
            }
            if (Cb != nullptr) {
                if (row0 < M)
                    *(__nv_bfloat162*)(Cb + (size_t)row0 * N + col) =
                        __nv_bfloat162(__float2bfloat16(v0), __float2bfloat16(v1));
                if (row1 < M)
                    *(__nv_bfloat162*)(Cb + (size_t)row1 * N + col) =
                        __nv_bfloat162(__float2bfloat16(v2), __float2bfloat16(v3));
            } else {
                if (row0 < M) *(float2*)(C + (size_t)row0 * N + col) = make_float2(v0, v1);
                if (row1 < M) *(float2*)(C + (size_t)row1 * N + col) = make_float2(v2, v3);
            }
        }
    }
}

// ---------------- fused edge kernel: score + softmax + gather per node ------
// warp per node, CSR in-edges. xr[node] cached in registers; denom in-warp;
// ex staged in smem (fast path deg<=MAXDEG, exact recompute fallback beyond).
__global__ void __launch_bounds__(256)
edge_fused(const float* __restrict__ We, const float* __restrict__ att,
           const float* __restrict__ bias)
{
    __shared__ float4 sWe[HID / 4];
    __shared__ float4 sAtt[HID / 4];
    __shared__ float  sEx[8][MAXDEG][HH];   // 16KB

    for (int i = threadIdx.x; i < HID / 4; i += blockDim.x) {
        sWe[i]  = ((const float4*)We)[i];
        sAtt[i] = ((const float4*)att)[i];
    }
    __syncthreads();

    const int wid  = threadIdx.x >> 5;
    const int lane = threadIdx.x & 31;
    const int node = blockIdx.x * 8 + wid;
    if (node >= NN) return;

    const int head = lane >> 2;
    const int st = g_offs[node], en = g_offs[node + 1];

    // xr[node] slice: 16 channels per lane
    float4 xr4[4];
    {
        const float4* xrp = (const float4*)(g_xr + (size_t)node * HID) + lane * 4;
#pragma unroll
        for (int q = 0; q < 4; q++) xr4[q] = xrp[q];
    }

    float4 we4[4], at4[4];
#pragma unroll
    for (int q = 0; q < 4; q++) { we4[q] = sWe[lane * 4 + q]; at4[q] = sAtt[lane * 4 + q]; }

    // pass 1: alpha -> ex, denom
    float denom = 0.f;
    for (int j = st; j < en; j++) {
        int s = g_csrc[j];
        float dv = g_cdist[j];
        const float4* xls = (const float4*)(g_xl + (size_t)s * HID) + lane * 4;
        float partial = 0.f;
#pragma unroll
        for (int q = 0; q < 4; q++) {
            float4 a = xls[q], b = xr4[q], w = we4[q], t = at4[q];
            float v;
            v = a.x + b.x + dv * w.x; v = v > 0.f ? v : 0.2f * v; partial += v * t.x;
            v = a.y + b.y + dv * w.y; v = v > 0.f ? v : 0.2f * v; partial += v * t.y;
            v = a.z + b.z + dv * w.z; v = v > 0.f ? v : 0.2f * v; partial += v * t.z;
            v = a.w + b.w + dv * w.w; v = v > 0.f ? v : 0.2f * v; partial += v * t.w;
        }
        partial += __shfl_xor_sync(0xffffffffu, partial, 1);
        partial += __shfl_xor_sync(0xffffffffu, partial, 2);
        float ex = expf(partial);       // softmax shift-invariant; scores O(1)
        denom += ex;
        int jj = j - st;
        if (jj < MAXDEG && (lane & 3) == 0) sEx[wid][jj][head] = ex;
    }
    const float inv = 1.f / denom;      // self-loop => denom > 0
    __syncwarp();

    // pass 2: weighted gather
    float4 acc[4];
#pragma unroll
    for (int q = 0; q < 4; q++) acc[q] = make_float4(0.f, 0.f, 0.f, 0.f);

    for (int j = st; j < en; j++) {
        int s = g_csrc[j];
        const float4* xls = (const float4*)(g_xl + (size_t)s * HID) + lane * 4;
        float w;
        int jj = j - st;
        if (jj < MAXDEG) {
            w = sEx[wid][jj][head] * inv;
        } else {                        // exact recompute fallback (deg > 64)
            float dv = g_cdist[j];
            float partial = 0.f;
#pragma unroll
            for (int q = 0; q < 4; q++) {
                float4 a = xls[q], b = xr4[q], ww = we4[q], t = at4[q];
                float v;
                v = a.x + b.x + dv * ww.x; v = v > 0.f ? v : 0.2f * v; partial += v * t.x;
                v = a.y + b.y + dv * ww.y; v = v > 0.f ? v : 0.2f * v; partial += v * t.y;
                v = a.z + b.z + dv * ww.z; v = v > 0.f ? v : 0.2f * v; partial += v * t.z;
                v = a.w + b.w + dv * ww.w; v = v > 0.f ? v : 0.2f * v; partial += v * t.w;
            }
            partial += __shfl_xor_sync(0xffffffffu, partial, 1);
            partial += __shfl_xor_sync(0xffffffffu, partial, 2);
            w = expf(partial) * inv;
        }
        float4 a0 = xls[0], a1 = xls[1], a2 = xls[2], a3 = xls[3];
        acc[0].x += w * a0.x; acc[0].y += w * a0.y; acc[0].z += w * a0.z; acc[0].w += w * a0.w;
        acc[1].x += w * a1.x; acc[1].y += w * a1.y; acc[1].z += w * a1.z; acc[1].w += w * a1.w;
        acc[2].x += w * a2.x; acc[2].y += w * a2.y; acc[2].z += w * a2.z; acc[2].w += w * a2.w;
        acc[3].x += w * a3.x; acc[3].y += w * a3.y; acc[3].z += w * a3.z; acc[3].w += w * a3.w;
    }

    // bias + elu, write fp32 h and bf16 hb
    const float4* b4 = (const float4*)bias + lane * 4;
    float* hp  = g_h  + (size_t)node * HID + lane * 16;
    bf16*  hbp = g_hb + (size_t)node * HID + lane * 16;
#pragma unroll
    for (int q = 0; q < 4; q++) {
        float4 b = b4[q];
        float4 v = acc[q];
        v.x += b.x; v.y += b.y; v.z += b.z; v.w += b.w;
        v.x = v.x > 0.f ? v.x : expm1f(v.x);
        v.y = v.y > 0.f ? v.y : expm1f(v.y);
        v.z = v.z > 0.f ? v.z : expm1f(v.z);
        v.w = v.w > 0.f ? v.w : expm1f(v.w);
        *(float4*)(hp + q * 4) = v;
        __nv_bfloat162 p0(__float2bfloat16(v.x), __float2bfloat16(v.y));
        __nv_bfloat162 p1(__float2bfloat16(v.z), __float2bfloat16(v.w));
        *(__nv_bfloat162*)(hbp + q * 4)     = p0;
        *(__nv_bfloat162*)(hbp + q * 4 + 2) = p1;
    }
}

// ---------------- final: logits = h @ Wa + ba; log_softmax -------------------
__global__ void final_kernel(const float* __restrict__ Wa,
                             const float* __restrict__ ba,
                             float* __restrict__ out)
{
    const int row = blockIdx.x * (blockDim.x >> 5) + (threadIdx.x >> 5);
    const int lane = threadIdx.x & 31;
    if (row >= NN) return;

    const float* hrow = g_h + (size_t)row * HID;
    float acc[NCLS];
#pragma unroll
    for (int c = 0; c < NCLS; c++) acc[c] = 0.f;

    for (int k = lane; k < HID; k += 32) {
        float hv = hrow[k];
        const float* wrow = Wa + (size_t)k * NCLS;
#pragma unroll
        for (int c = 0; c < NCLS; c++) acc[c] += hv * wrow[c];
    }
#pragma unroll
    for (int off = 16; off > 0; off >>= 1)
#pragma unroll
        for (int c = 0; c < NCLS; c++)
            acc[c] += __shfl_xor_sync(0xffffffffu, acc[c], off);

    if (lane == 0) {
        float z[NCLS], mx = -1e30f;
#pragma unroll
        for (int c = 0; c < NCLS; c++) { z[c] = acc[c] + ba[c]; mx = fmaxf(mx, z[c]); }
        float s = 0.f;
#pragma unroll
        for (int c = 0; c < NCLS; c++) s += expf(z[c] - mx);
        float lse = mx + logf(s);
#pragma unroll
        for (int c = 0; c < NCLS; c++) out[(size_t)row * NCLS + c] = z[c] - lse;
    }
}

// ---------------- launch ----------------
extern "C" void kernel_launch(void* const* d_in, const int* in_sizes, int n_in,
                              void* d_out, int out_size)
{
    const float* x    = (const float*)d_in[0];
    const int*   ei   = (const int*)d_in[1];      // int32 (JAX x64 disabled)
    const float* dist = (const float*)d_in[2];
    const float* Wb   = (const float*)d_in[3];
    const float* bb   = (const float*)d_in[4];
    const float* Wl   = (const float*)d_in[5];
    const float* bl   = (const float*)d_in[6];
    const float* Wr   = (const float*)d_in[7];
    const float* br   = (const float*)d_in[8];
    const float* We   = (const float*)d_in[9];
    const float* att  = (const float*)d_in[10];
    const float* bc   = (const float*)d_in[11];
    const float* Wa   = (const float*)d_in[12];
    const float* ba   = (const float*)d_in[13];
    float* out = (float*)d_out;

    float *pxl, *pxr;
    bf16 *phb, *pxb, *pwbT, *pwlT, *pwrT;
    int *pcnt, *poffs, *pcur;
    cudaGetSymbolAddress((void**)&pxl,  g_xl);
    cudaGetSymbolAddress((void**)&pxr,  g_xr);
    cudaGetSymbolAddress((void**)&phb,  g_hb);
    cudaGetSymbolAddress((void**)&pxb,  g_xb);
    cudaGetSymbolAddress((void**)&pwbT, g_wbT);
    cudaGetSymbolAddress((void**)&pwlT, g_wlT);
    cudaGetSymbolAddress((void**)&pwrT, g_wrT);
    cudaGetSymbolAddress((void**)&pcnt, g_cnt);
    cudaGetSymbolAddress((void**)&poffs, g_offs);
    cudaGetSymbolAddress((void**)&pcur, g_cursor);

    // ---- prep: conversions + transposes + CSR ----
    conv_x_kernel<<<(NN * FIN + 255) / 256, 256>>>(x);
    dim3 tb(32, 8);
    transp_bf16<<<dim3(HID / 32, FIN / 32), tb>>>(Wb, pwbT, FIN, HID);
    transp_bf16_batch6<<<dim3(HID / 32, HID / 32, 6), tb>>>(Wl, Wr);
    zero_i<<<(NN + 255) / 256, 256>>>(pcnt, NN);
    hist_kernel<<<(ETOT + 255) / 256, 256>>>(ei);
    scan_kernel<<<1, 1024>>>();
    copy_i<<<(NN + 255) / 256, 256>>>(poffs, pcur, NN);
    scatter_kernel<<<(ETOT + 255) / 256, 256>>>(ei, dist);

    // ---- fcnn_before: hb = bf16(elu(x @ Wb + bb)) ----
    bf16gemm<<<dim3(HID / 128, (NN + 127) / 128), 256>>>(
        pxb, pwbT, nullptr, bb, nullptr, nullptr, nullptr, phb, NN, FIN, 1);

    for (int i = 0; i < 3; i++) {
        // fused dual GEMM: xl = hb @ Wl^T + bl ; xr = hb @ Wr^T + br (fp32 out)
        bf16gemm<<<dim3(2 * HID / 128, (NN + 127) / 128), 256>>>(
            phb, pwlT + (size_t)i * HID * HID, pwrT + (size_t)i * HID * HID,
            bl + i * HID, br + i * HID, pxl, pxr, nullptr, NN, HID, 0);
        edge_fused<<<(NN + 7) / 8, 256>>>(We + (size_t)i * HID,
                                          att + (size_t)i * HID,
                                          bc + (size_t)i * HID);
    }

    final_kernel<<<(NN + 7) / 8, 256>>>(Wa, ba, out);
}

// round 9
// speedup vs baseline: 6.6718x; 1.3289x over previous
#include <cuda_runtime.h>
#include <cuda_bf16.h>
#include <math.h>
#include <stdint.h>

typedef __nv_bfloat16 bf16;

#define NN   10000
#define EE   160000
#define ETOT 170000   // EE + NN self loops
#define FIN  128
#define HID  512
#define HH   8
#define CC   64
#define NCLS 10

// ---------------- scratch (device globals; no allocs allowed) ----------------
__device__ float g_h [NN * HID];          // fp32 h (for final layer)
__device__ bf16  g_hb[NN * HID];          // bf16 h (GEMM A input)
__device__ bf16  g_xb[NN * FIN];          // bf16 x
__device__ float g_xl[NN * HID];
__device__ float g_xr[NN * HID];
__device__ bf16  g_wbT[HID * FIN];        // Wb^T  [n][k]
__device__ bf16  g_wlT[3 * HID * HID];    // Wl^T per layer
__device__ bf16  g_wrT[3 * HID * HID];    // Wr^T per layer
__device__ int   g_cnt[NN];
__device__ int   g_offs[NN + 1];
__device__ int   g_cursor[NN];
__device__ int   g_csrc[ETOT];
__device__ float g_cdist[ETOT];

// ---------------- small helpers ----------------
__global__ void zero_i(int* __restrict__ p, int n)
{
    int i = blockIdx.x * blockDim.x + threadIdx.x;
    if (i < n) p[i] = 0;
}
__global__ void copy_i(const int* __restrict__ a, int* __restrict__ b, int n)
{
    int i = blockIdx.x * blockDim.x + threadIdx.x;
    if (i < n) b[i] = a[i];
}
__global__ void conv_x_kernel(const float* __restrict__ x)
{
    int i = blockIdx.x * blockDim.x + threadIdx.x;
    if (i < NN * FIN) g_xb[i] = __float2bfloat16(x[i]);
}

// transpose+convert: dst[n][k] = bf16(src[k][n]); K,N multiples of 32
__global__ void transp_bf16(const float* __restrict__ src, bf16* __restrict__ dst,
                            int K, int N)
{
    __shared__ float tile[32][33];
    int k0 = blockIdx.y * 32, n0 = blockIdx.x * 32;
    int tx = threadIdx.x, ty = threadIdx.y;   // 32 x 8
#pragma unroll
    for (int i = 0; i < 32; i += 8)
        tile[ty + i][tx] = src[(size_t)(k0 + ty + i) * N + n0 + tx];
    __syncthreads();
#pragma unroll
    for (int i = 0; i < 32; i += 8)
        dst[(size_t)(n0 + ty + i) * K + k0 + tx] = __float2bfloat16(tile[tx][ty + i]);
}

// batched version for the six HID x HID weight matrices (Wl 0..2, Wr 0..2)
__global__ void transp_bf16_batch6(const float* __restrict__ Wl,
                                   const float* __restrict__ Wr)
{
    __shared__ float tile[32][33];
    int z = blockIdx.z;
    const float* src = (z < 3) ? Wl + (size_t)z * HID * HID
                               : Wr + (size_t)(z - 3) * HID * HID;
    bf16* dst = (z < 3) ? g_wlT + (size_t)z * HID * HID
                        : g_wrT + (size_t)(z - 3) * HID * HID;
    int k0 = blockIdx.y * 32, n0 = blockIdx.x * 32;
    int tx = threadIdx.x, ty = threadIdx.y;
#pragma unroll
    for (int i = 0; i < 32; i += 8)
        tile[ty + i][tx] = src[(size_t)(k0 + ty + i) * HID + n0 + tx];
    __syncthreads();
#pragma unroll
    for (int i = 0; i < 32; i += 8)
        dst[(size_t)(n0 + ty + i) * HID + k0 + tx] = __float2bfloat16(tile[tx][ty + i]);
}

// ---------------- CSR build ----------------
__global__ void hist_kernel(const int* __restrict__ ei)
{
    int e = blockIdx.x * blockDim.x + threadIdx.x;
    if (e >= ETOT) return;
    int d = (e < EE) ? ei[EE + e] : e - EE;
    atomicAdd(&g_cnt[d], 1);
}

__global__ void scan_kernel()   // 1 block, 1024 threads; exclusive scan of g_cnt
{
    __shared__ int warpsum[32];
    __shared__ int carry;
    if (threadIdx.x == 0) carry = 0;
    __syncthreads();
    int lane = threadIdx.x & 31, wid = threadIdx.x >> 5;
    for (int base = 0; base < NN; base += 1024) {
        int i = base + threadIdx.x;
        int v = (i < NN) ? g_cnt[i] : 0;
        int x = v;
#pragma unroll
        for (int o = 1; o < 32; o <<= 1) {
            int y = __shfl_up_sync(0xffffffffu, x, o);
            if (lane >= o) x += y;
        }
        if (lane == 31) warpsum[wid] = x;
        __syncthreads();
        if (wid == 0) {
            int s = warpsum[lane];
#pragma unroll
            for (int o = 1; o < 32; o <<= 1) {
                int y = __shfl_up_sync(0xffffffffu, s, o);
                if (lane >= o) s += y;
            }
            warpsum[lane] = s;
        }
        __syncthreads();
        int pre = (wid > 0) ? warpsum[wid - 1] : 0;
        int incl = x + pre + carry;
        if (i < NN) g_offs[i] = incl - v;
        __syncthreads();
        if (threadIdx.x == 1023) carry = incl;
        __syncthreads();
    }
    if (threadIdx.x == 0) g_offs[NN] = carry;
}

__global__ void scatter_kernel(const int* __restrict__ ei,
                               const float* __restrict__ dist)
{
    int e = blockIdx.x * blockDim.x + threadIdx.x;
    if (e >= ETOT) return;
    int s, d; float dv;
    if (e < EE) { s = ei[e]; d = ei[EE + e]; dv = dist[e]; }
    else        { s = d = e - EE; dv = 0.f; }
    int pos = atomicAdd(&g_cursor[d], 1);
    g_csrc[pos] = s;
    g_cdist[pos] = dv;
}

// ---------------- bf16 tensor-core GEMM -------------------------------------
// C[M,N] = A[M,K] @ B^T, B stored [N][K] bf16 (pre-transposed weights).
// 128x128 tile, 256 thr, K-chunk 32, 3-stage cp.async ring (1 barrier/chunk).
__device__ __forceinline__ void mma_bf16(float* c, const uint32_t* a, const uint32_t* b)
{
    asm volatile(
        "mma.sync.aligned.m16n8k16.row.col.f32.bf16.bf16.f32 "
        "{%0,%1,%2,%3}, {%4,%5,%6,%7}, {%8,%9}, {%0,%1,%2,%3};"
        : "+f"(c[0]), "+f"(c[1]), "+f"(c[2]), "+f"(c[3])
        : "r"(a[0]), "r"(a[1]), "r"(a[2]), "r"(a[3]), "r"(b[0]), "r"(b[1]));
}
__device__ __forceinline__ void cp16(uint32_t dst, const void* src)
{
    asm volatile("cp.async.cg.shared.global [%0], [%1], 16;" :: "r"(dst), "l"(src));
}

#define STAGE_BYTES 20480                  // A: 128*80 + B: 128*80
#define GEMM_SMEM   (3 * STAGE_BYTES)      // 61440, dynamic

__global__ void __launch_bounds__(256, 2)
bf16gemm(const bf16* __restrict__ A,
         const bf16* __restrict__ B0, const bf16* __restrict__ B1,
         const float* __restrict__ bias0, const float* __restrict__ bias1,
         float* __restrict__ C0, float* __restrict__ C1, bf16* __restrict__ Cb,
         int M, int K, int doElu)
{
    extern __shared__ __align__(16) unsigned char smem[];
    const int N = HID;

    const int tid  = threadIdx.x;
    const int wid  = tid >> 5;
    const int lane = tid & 31;
    const int g    = lane >> 2;
    const int tg   = lane & 3;

    const bf16* B = B0;
    float* C = C0;
    const float* bi = bias0;
    int bx = blockIdx.x;
    if (B1 != nullptr && bx >= ((int)gridDim.x >> 1)) {
        B = B1; C = C1; bi = bias1; bx -= (int)gridDim.x >> 1;
    }
    const int m0 = blockIdx.y * 128;
    const int n0 = bx * 128;
    const int warpM = (wid >> 2) * 64;
    const int warpN = (wid & 3) * 32;

    const uint32_t sbase = (uint32_t)__cvta_generic_to_shared(smem);

    const int lrow = tid >> 2;          // row for i=0 (0..63); i adds 64
    const int lq   = tid & 3;

    float acc[4][4][4];
#pragma unroll
    for (int mt = 0; mt < 4; mt++)
#pragma unroll
        for (int nt = 0; nt < 4; nt++)
#pragma unroll
            for (int i = 0; i < 4; i++) acc[mt][nt][i] = 0.f;

    const int nStages = K >> 5;

    auto issue = [&](int buf, int ks) {
        uint32_t sA = sbase + buf * STAGE_BYTES;
        uint32_t sB = sA + 10240;
        int k0 = ks << 5;
#pragma unroll
        for (int i = 0; i < 2; i++) {
            int row = lrow + i * 64;
            int ar = m0 + row; if (ar >= M) ar = M - 1;
            cp16(sA + row * 80 + lq * 16, A + (size_t)ar * K + k0 + lq * 8);
            cp16(sB + row * 80 + lq * 16, B + (size_t)(n0 + row) * K + k0 + lq * 8);
        }
        asm volatile("cp.async.commit_group;");
    };

    issue(0, 0);
    if (nStages > 1) issue(1, 1);

    for (int ks = 0; ks < nStages; ks++) {
        if (ks + 1 < nStages)
            asm volatile("cp.async.wait_group 1;");
        else
            asm volatile("cp.async.wait_group 0;");
        __syncthreads();

        const uint32_t* As32 = (const uint32_t*)(smem + (ks % 3) * STAGE_BYTES);
        const uint32_t* Bs32 = (const uint32_t*)(smem + (ks % 3) * STAGE_BYTES + 10240);

#pragma unroll
        for (int kk = 0; kk < 32; kk += 16) {
            const int j0 = kk >> 1;
            uint32_t a[4][4], b[4][2];
#pragma unroll
            for (int mt = 0; mt < 4; mt++) {
                int mr = warpM + mt * 16 + g;
                a[mt][0] = As32[mr * 20 + j0 + tg];
                a[mt][1] = As32[(mr + 8) * 20 + j0 + tg];
                a[mt][2] = As32[mr * 20 + j0 + tg + 4];
                a[mt][3] = As32[(mr + 8) * 20 + j0 + tg + 4];
            }
#pragma unroll
            for (int nt = 0; nt < 4; nt++) {
                int nc = warpN + nt * 8 + g;
                b[nt][0] = Bs32[nc * 20 + j0 + tg];
                b[nt][1] = Bs32[nc * 20 + j0 + tg + 4];
            }
#pragma unroll
            for (int mt = 0; mt < 4; mt++)
#pragma unroll
                for (int nt = 0; nt < 4; nt++)
                    mma_bf16(acc[mt][nt], a[mt], b[nt]);
        }

        if (ks + 2 < nStages) issue((ks + 2) % 3, ks + 2);
    }

#pragma unroll
    for (int mt = 0; mt < 4; mt++) {
        int row0 = m0 + warpM + mt * 16 + g;
        int row1 = row0 + 8;
#pragma unroll
        for (int nt = 0; nt < 4; nt++) {
            int col = n0 + warpN + nt * 8 + tg * 2;
            float bx0 = bi[col], bx1 = bi[col + 1];
            float v0 = acc[mt][nt][0] + bx0;
            float v1 = acc[mt][nt][1] + bx1;
            float v2 = acc[mt][nt][2] + bx0;
            float v3 = acc[mt][nt][3] + bx1;
            if (doElu) {
                v0 = v0 > 0.f ? v0 : expm1f(v0);
                v1 = v1 > 0.f ? v1 : expm1f(v1);
                v2 = v2 > 0.f ? v2 : expm1f(v2);
                v3 = v3 > 0.f ? v3 : expm1f(v3);
            }
            if (Cb != nullptr) {
                if (row0 < M)
                    *(__nv_bfloat162*)(Cb + (size_t)row0 * N + col) =
                        __nv_bfloat162(__float2bfloat16(v0), __float2bfloat16(v1));
                if (row1 < M)
                    *(__nv_bfloat162*)(Cb + (size_t)row1 * N + col) =
                        __nv_bfloat162(__float2bfloat16(v2), __float2bfloat16(v3));
            } else {
                if (row0 < M) *(float2*)(C + (size_t)row0 * N + col) = make_float2(v0, v1);
                if (row1 < M) *(float2*)(C + (size_t)row1 * N + col) = make_float2(v2, v3);
            }
        }
    }
}

// ---------------- fused edge kernel: single pass ----------------------------
// softmax linearity: out = (sum_e ex_e * xl[src_e]) / denom  — so score and
// weighted accumulation share one loop (xl row already in registers).
__global__ void __launch_bounds__(256)
edge_fused(const float* __restrict__ We, const float* __restrict__ att,
           const float* __restrict__ bias)
{
    __shared__ float4 sWe[HID / 4];
    __shared__ float4 sAtt[HID / 4];

    for (int i = threadIdx.x; i < HID / 4; i += blockDim.x) {
        sWe[i]  = ((const float4*)We)[i];
        sAtt[i] = ((const float4*)att)[i];
    }
    __syncthreads();

    const int wid  = threadIdx.x >> 5;
    const int lane = threadIdx.x & 31;
    const int node = blockIdx.x * 8 + wid;
    if (node >= NN) return;

    const int st = g_offs[node], en = g_offs[node + 1];

    float4 xr4[4];
    {
        const float4* xrp = (const float4*)(g_xr + (size_t)node * HID) + lane * 4;
#pragma unroll
        for (int q = 0; q < 4; q++) xr4[q] = xrp[q];
    }
    float4 we4[4], at4[4];
#pragma unroll
    for (int q = 0; q < 4; q++) { we4[q] = sWe[lane * 4 + q]; at4[q] = sAtt[lane * 4 + q]; }

    float denom = 0.f;
    float4 acc[4];
#pragma unroll
    for (int q = 0; q < 4; q++) acc[q] = make_float4(0.f, 0.f, 0.f, 0.f);

    for (int j = st; j < en; j++) {
        int s = g_csrc[j];
        float dv = g_cdist[j];
        const float4* xls = (const float4*)(g_xl + (size_t)s * HID) + lane * 4;
        float4 a0 = xls[0], a1 = xls[1], a2 = xls[2], a3 = xls[3];

        float partial = 0.f;
        {
            float v;
            float4 b = xr4[0], w = we4[0], t = at4[0];
            v = a0.x + b.x + dv * w.x; v = v > 0.f ? v : 0.2f * v; partial += v * t.x;
            v = a0.y + b.y + dv * w.y; v = v > 0.f ? v : 0.2f * v; partial += v * t.y;
            v = a0.z + b.z + dv * w.z; v = v > 0.f ? v : 0.2f * v; partial += v * t.z;
            v = a0.w + b.w + dv * w.w; v = v > 0.f ? v : 0.2f * v; partial += v * t.w;
            b = xr4[1]; w = we4[1]; t = at4[1];
            v = a1.x + b.x + dv * w.x; v = v > 0.f ? v : 0.2f * v; partial += v * t.x;
            v = a1.y + b.y + dv * w.y; v = v > 0.f ? v : 0.2f * v; partial += v * t.y;
            v = a1.z + b.z + dv * w.z; v = v > 0.f ? v : 0.2f * v; partial += v * t.z;
            v = a1.w + b.w + dv * w.w; v = v > 0.f ? v : 0.2f * v; partial += v * t.w;
            b = xr4[2]; w = we4[2]; t = at4[2];
            v = a2.x + b.x + dv * w.x; v = v > 0.f ? v : 0.2f * v; partial += v * t.x;
            v = a2.y + b.y + dv * w.y; v = v > 0.f ? v : 0.2f * v; partial += v * t.y;
            v = a2.z + b.z + dv * w.z; v = v > 0.f ? v : 0.2f * v; partial += v * t.z;
            v = a2.w + b.w + dv * w.w; v = v > 0.f ? v : 0.2f * v; partial += v * t.w;
            b = xr4[3]; w = we4[3]; t = at4[3];
            v = a3.x + b.x + dv * w.x; v = v > 0.f ? v : 0.2f * v; partial += v * t.x;
            v = a3.y + b.y + dv * w.y; v = v > 0.f ? v : 0.2f * v; partial += v * t.y;
            v = a3.z + b.z + dv * w.z; v = v > 0.f ? v : 0.2f * v; partial += v * t.z;
            v = a3.w + b.w + dv * w.w; v = v > 0.f ? v : 0.2f * v; partial += v * t.w;
        }
        partial += __shfl_xor_sync(0xffffffffu, partial, 1);
        partial += __shfl_xor_sync(0xffffffffu, partial, 2);
        float ex = expf(partial);   // softmax shift-invariant; scores O(1)
        denom += ex;
        acc[0].x += ex * a0.x; acc[0].y += ex * a0.y; acc[0].z += ex * a0.z; acc[0].w += ex * a0.w;
        acc[1].x += ex * a1.x; acc[1].y += ex * a1.y; acc[1].z += ex * a1.z; acc[1].w += ex * a1.w;
        acc[2].x += ex * a2.x; acc[2].y += ex * a2.y; acc[2].z += ex * a2.z; acc[2].w += ex * a2.w;
        acc[3].x += ex * a3.x; acc[3].y += ex * a3.y; acc[3].z += ex * a3.z; acc[3].w += ex * a3.w;
    }

    const float inv = 1.f / denom;      // self-loop => denom > 0

    const float4* b4 = (const float4*)bias + lane * 4;
    float* hp  = g_h  + (size_t)node * HID + lane * 16;
    bf16*  hbp = g_hb + (size_t)node * HID + lane * 16;
#pragma unroll
    for (int q = 0; q < 4; q++) {
        float4 b = b4[q];
        float4 v = acc[q];
        v.x = v.x * inv + b.x; v.y = v.y * inv + b.y;
        v.z = v.z * inv + b.z; v.w = v.w * inv + b.w;
        v.x = v.x > 0.f ? v.x : expm1f(v.x);
        v.y = v.y > 0.f ? v.y : expm1f(v.y);
        v.z = v.z > 0.f ? v.z : expm1f(v.z);
        v.w = v.w > 0.f ? v.w : expm1f(v.w);
        *(float4*)(hp + q * 4) = v;
        __nv_bfloat162 p0(__float2bfloat16(v.x), __float2bfloat16(v.y));
        __nv_bfloat162 p1(__float2bfloat16(v.z), __float2bfloat16(v.w));
        *(__nv_bfloat162*)(hbp + q * 4)     = p0;
        *(__nv_bfloat162*)(hbp + q * 4 + 2) = p1;
    }
}

// ---------------- final: logits = h @ Wa + ba; log_softmax -------------------
__global__ void final_kernel(const float* __restrict__ Wa,
                             const float* __restrict__ ba,
                             float* __restrict__ out)
{
    const int row = blockIdx.x * (blockDim.x >> 5) + (threadIdx.x >> 5);
    const int lane = threadIdx.x & 31;
    if (row >= NN) return;

    const float* hrow = g_h + (size_t)row * HID;
    float acc[NCLS];
#pragma unroll
    for (int c = 0; c < NCLS; c++) acc[c] = 0.f;

    for (int k = lane; k < HID; k += 32) {
        float hv = hrow[k];
        const float* wrow = Wa + (size_t)k * NCLS;
#pragma unroll
        for (int c = 0; c < NCLS; c++) acc[c] += hv * wrow[c];
    }
#pragma unroll
    for (int off = 16; off > 0; off >>= 1)
#pragma unroll
        for (int c = 0; c < NCLS; c++)
            acc[c] += __shfl_xor_sync(0xffffffffu, acc[c], off);

    if (lane == 0) {
        float z[NCLS], mx = -1e30f;
#pragma unroll
        for (int c = 0; c < NCLS; c++) { z[c] = acc[c] + ba[c]; mx = fmaxf(mx, z[c]); }
        float s = 0.f;
#pragma unroll
        for (int c = 0; c < NCLS; c++) s += expf(z[c] - mx);
        float lse = mx + logf(s);
#pragma unroll
        for (int c = 0; c < NCLS; c++) out[(size_t)row * NCLS + c] = z[c] - lse;
    }
}

// ---------------- launch ----------------
extern "C" void kernel_launch(void* const* d_in, const int* in_sizes, int n_in,
                              void* d_out, int out_size)
{
    const float* x    = (const float*)d_in[0];
    const int*   ei   = (const int*)d_in[1];      // int32 (JAX x64 disabled)
    const float* dist = (const float*)d_in[2];
    const float* Wb   = (const float*)d_in[3];
    const float* bb   = (const float*)d_in[4];
    const float* Wl   = (const float*)d_in[5];
    const float* bl   = (const float*)d_in[6];
    const float* Wr   = (const float*)d_in[7];
    const float* br   = (const float*)d_in[8];
    const float* We   = (const float*)d_in[9];
    const float* att  = (const float*)d_in[10];
    const float* bc   = (const float*)d_in[11];
    const float* Wa   = (const float*)d_in[12];
    const float* ba   = (const float*)d_in[13];
    float* out = (float*)d_out;

    float *pxl, *pxr;
    bf16 *phb, *pxb, *pwbT, *pwlT, *pwrT;
    int *pcnt, *poffs, *pcur;
    cudaGetSymbolAddress((void**)&pxl,  g_xl);
    cudaGetSymbolAddress((void**)&pxr,  g_xr);
    cudaGetSymbolAddress((void**)&phb,  g_hb);
    cudaGetSymbolAddress((void**)&pxb,  g_xb);
    cudaGetSymbolAddress((void**)&pwbT, g_wbT);
    cudaGetSymbolAddress((void**)&pwlT, g_wlT);
    cudaGetSymbolAddress((void**)&pwrT, g_wrT);
    cudaGetSymbolAddress((void**)&pcnt, g_cnt);
    cudaGetSymbolAddress((void**)&poffs, g_offs);
    cudaGetSymbolAddress((void**)&pcur, g_cursor);

    cudaFuncSetAttribute(bf16gemm, cudaFuncAttributeMaxDynamicSharedMemorySize, GEMM_SMEM);

    // ---- prep (ordered so ncu -s 5 -c 1 captures the fcnn bf16gemm) ----
    conv_x_kernel<<<(NN * FIN + 255) / 256, 256>>>(x);                      // 1
    dim3 tb(32, 8);
    transp_bf16<<<dim3(HID / 32, FIN / 32), tb>>>(Wb, pwbT, FIN, HID);      // 2
    transp_bf16_batch6<<<dim3(HID / 32, HID / 32, 6), tb>>>(Wl, Wr);        // 3
    zero_i<<<(NN + 255) / 256, 256>>>(pcnt, NN);                            // 4
    hist_kernel<<<(ETOT + 255) / 256, 256>>>(ei);                           // 5
    // fcnn_before: hb = bf16(elu(x @ Wb + bb))                              // 6
    bf16gemm<<<dim3(HID / 128, (NN + 127) / 128), 256, GEMM_SMEM>>>(
        pxb, pwbT, nullptr, bb, nullptr, nullptr, nullptr, phb, NN, FIN, 1);
    scan_kernel<<<1, 1024>>>();                                             // 7
    copy_i<<<(NN + 255) / 256, 256>>>(poffs, pcur, NN);                     // 8
    scatter_kernel<<<(ETOT + 255) / 256, 256>>>(ei, dist);                  // 9

    for (int i = 0; i < 3; i++) {
        // fused dual GEMM: xl = hb @ Wl^T + bl ; xr = hb @ Wr^T + br (fp32 out)
        bf16gemm<<<dim3(2 * HID / 128, (NN + 127) / 128), 256, GEMM_SMEM>>>(
            phb, pwlT + (size_t)i * HID * HID, pwrT + (size_t)i * HID * HID,
            bl + i * HID, br + i * HID, pxl, pxr, nullptr, NN, HID, 0);
        edge_fused<<<(NN + 7) / 8, 256>>>(We + (size_t)i * HID,
                                          att + (size_t)i * HID,
                                          bc + (size_t)i * HID);
    }

    final_kernel<<<(NN + 7) / 8, 256>>>(Wa, ba, out);
}

// round 10
// speedup vs baseline: 7.0334x; 1.0542x over previous
#include <cuda_runtime.h>
#include <cuda_bf16.h>
#include <math.h>
#include <stdint.h>

typedef __nv_bfloat16 bf16;

#define NN   10000
#define EE   160000
#define ETOT 170000   // EE + NN self loops
#define FIN  128
#define HID  512
#define HH   8
#define CC   64
#define NCLS 10

// ---------------- scratch (device globals; no allocs allowed) ----------------
__device__ float g_h [NN * HID];          // fp32 h (final layer only)
__device__ bf16  g_hb[NN * HID];          // bf16 h (GEMM A input)
__device__ bf16  g_xb[NN * FIN];          // bf16 x
__device__ float g_xl[NN * HID];
__device__ float g_xr[NN * HID];
__device__ bf16  g_wbT[HID * FIN];        // Wb^T  [n][k]
__device__ bf16  g_wlT[3 * HID * HID];    // Wl^T per layer
__device__ bf16  g_wrT[3 * HID * HID];    // Wr^T per layer
__device__ int   g_cnt[NN];
__device__ int   g_offs[NN + 1];
__device__ int   g_cursor[NN];
__device__ int   g_csrc[ETOT];
__device__ float g_cdist[ETOT];

// ---------------- small helpers ----------------
__global__ void zero_i(int* __restrict__ p, int n)
{
    int i = blockIdx.x * blockDim.x + threadIdx.x;
    if (i < n) p[i] = 0;
}
__global__ void copy_i(const int* __restrict__ a, int* __restrict__ b, int n)
{
    int i = blockIdx.x * blockDim.x + threadIdx.x;
    if (i < n) b[i] = a[i];
}
__global__ void conv_x_kernel(const float* __restrict__ x)
{
    int i = blockIdx.x * blockDim.x + threadIdx.x;
    if (i < NN * FIN) g_xb[i] = __float2bfloat16(x[i]);
}

// transpose+convert: dst[n][k] = bf16(src[k][n]); K,N multiples of 32
__global__ void transp_bf16(const float* __restrict__ src, bf16* __restrict__ dst,
                            int K, int N)
{
    __shared__ float tile[32][33];
    int k0 = blockIdx.y * 32, n0 = blockIdx.x * 32;
    int tx = threadIdx.x, ty = threadIdx.y;   // 32 x 8
#pragma unroll
    for (int i = 0; i < 32; i += 8)
        tile[ty + i][tx] = src[(size_t)(k0 + ty + i) * N + n0 + tx];
    __syncthreads();
#pragma unroll
    for (int i = 0; i < 32; i += 8)
        dst[(size_t)(n0 + ty + i) * K + k0 + tx] = __float2bfloat16(tile[tx][ty + i]);
}

// batched version for the six HID x HID weight matrices (Wl 0..2, Wr 0..2)
__global__ void transp_bf16_batch6(const float* __restrict__ Wl,
                                   const float* __restrict__ Wr)
{
    __shared__ float tile[32][33];
    int z = blockIdx.z;
    const float* src = (z < 3) ? Wl + (size_t)z * HID * HID
                               : Wr + (size_t)(z - 3) * HID * HID;
    bf16* dst = (z < 3) ? g_wlT + (size_t)z * HID * HID
                        : g_wrT + (size_t)(z - 3) * HID * HID;
    int k0 = blockIdx.y * 32, n0 = blockIdx.x * 32;
    int tx = threadIdx.x, ty = threadIdx.y;
#pragma unroll
    for (int i = 0; i < 32; i += 8)
        tile[ty + i][tx] = src[(size_t)(k0 + ty + i) * HID + n0 + tx];
    __syncthreads();
#pragma unroll
    for (int i = 0; i < 32; i += 8)
        dst[(size_t)(n0 + ty + i) * HID + k0 + tx] = __float2bfloat16(tile[tx][ty + i]);
}

// ---------------- CSR build ----------------
__global__ void hist_kernel(const int* __restrict__ ei)
{
    int e = blockIdx.x * blockDim.x + threadIdx.x;
    if (e >= ETOT) return;
    int d = (e < EE) ? ei[EE + e] : e - EE;
    atomicAdd(&g_cnt[d], 1);
}

__global__ void scan_kernel()   // 1 block, 1024 threads; exclusive scan of g_cnt
{
    __shared__ int warpsum[32];
    __shared__ int carry;
    if (threadIdx.x == 0) carry = 0;
    __syncthreads();
    int lane = threadIdx.x & 31, wid = threadIdx.x >> 5;
    for (int base = 0; base < NN; base += 1024) {
        int i = base + threadIdx.x;
        int v = (i < NN) ? g_cnt[i] : 0;
        int x = v;
#pragma unroll
        for (int o = 1; o < 32; o <<= 1) {
            int y = __shfl_up_sync(0xffffffffu, x, o);
            if (lane >= o) x += y;
        }
        if (lane == 31) warpsum[wid] = x;
        __syncthreads();
        if (wid == 0) {
            int s = warpsum[lane];
#pragma unroll
            for (int o = 1; o < 32; o <<= 1) {
                int y = __shfl_up_sync(0xffffffffu, s, o);
                if (lane >= o) s += y;
            }
            warpsum[lane] = s;
        }
        __syncthreads();
        int pre = (wid > 0) ? warpsum[wid - 1] : 0;
        int incl = x + pre + carry;
        if (i < NN) g_offs[i] = incl - v;
        __syncthreads();
        if (threadIdx.x == 1023) carry = incl;
        __syncthreads();
    }
    if (threadIdx.x == 0) g_offs[NN] = carry;
}

__global__ void scatter_kernel(const int* __restrict__ ei,
                               const float* __restrict__ dist)
{
    int e = blockIdx.x * blockDim.x + threadIdx.x;
    if (e >= ETOT) return;
    int s, d; float dv;
    if (e < EE) { s = ei[e]; d = ei[EE + e]; dv = dist[e]; }
    else        { s = d = e - EE; dv = 0.f; }
    int pos = atomicAdd(&g_cursor[d], 1);
    g_csrc[pos] = s;
    g_cdist[pos] = dv;
}

// ---------------- bf16 tensor-core GEMM -------------------------------------
// C[M,N] = A[M,K] @ B^T, B stored [N][K] bf16 (pre-transposed weights).
// 128x128 tile, 256 thr, K-chunk 32, 3-stage cp.async ring, ldmatrix fragments.
__device__ __forceinline__ void mma_bf16(float* c, const uint32_t* a, const uint32_t* b)
{
    asm volatile(
        "mma.sync.aligned.m16n8k16.row.col.f32.bf16.bf16.f32 "
        "{%0,%1,%2,%3}, {%4,%5,%6,%7}, {%8,%9}, {%0,%1,%2,%3};"
        : "+f"(c[0]), "+f"(c[1]), "+f"(c[2]), "+f"(c[3])
        : "r"(a[0]), "r"(a[1]), "r"(a[2]), "r"(a[3]), "r"(b[0]), "r"(b[1]));
}
__device__ __forceinline__ void cp16(uint32_t dst, const void* src)
{
    asm volatile("cp.async.cg.shared.global [%0], [%1], 16;" :: "r"(dst), "l"(src));
}
__device__ __forceinline__ void ldsm4(uint32_t* r, uint32_t addr)
{
    asm volatile("ldmatrix.sync.aligned.m8n8.x4.shared.b16 {%0,%1,%2,%3}, [%4];"
                 : "=r"(r[0]), "=r"(r[1]), "=r"(r[2]), "=r"(r[3]) : "r"(addr));
}

#define STAGE_BYTES 20480                  // A: 128*80 + B: 128*80
#define GEMM_SMEM   (3 * STAGE_BYTES)      // 61440, dynamic

__global__ void __launch_bounds__(256, 2)
bf16gemm(const bf16* __restrict__ A,
         const bf16* __restrict__ B0, const bf16* __restrict__ B1,
         const float* __restrict__ bias0, const float* __restrict__ bias1,
         float* __restrict__ C0, float* __restrict__ C1, bf16* __restrict__ Cb,
         int M, int K, int doElu)
{
    extern __shared__ __align__(16) unsigned char smem[];
    const int N = HID;

    const int tid  = threadIdx.x;
    const int wid  = tid >> 5;
    const int lane = tid & 31;
    const int g    = lane >> 2;
    const int tg   = lane & 3;

    const bf16* B = B0;
    float* C = C0;
    const float* bi = bias0;
    int bx = blockIdx.x;
    if (B1 != nullptr && bx >= ((int)gridDim.x >> 1)) {
        B = B1; C = C1; bi = bias1; bx -= (int)gridDim.x >> 1;
    }
    const int m0 = blockIdx.y * 128;
    const int n0 = bx * 128;
    const int warpM = (wid >> 2) * 64;
    const int warpN = (wid & 3) * 32;

    const uint32_t sbase = (uint32_t)__cvta_generic_to_shared(smem);

    const int lrow = tid >> 2;          // cp.async row for i=0; i adds 64
    const int lq   = tid & 3;

    // ldmatrix per-lane address offsets (within a stage buffer)
    // A (x4, one per mt): lanes 0-15 rows 0-15 (k-lo), lanes 16-31 same rows k-hi
    uint32_t aOff[4];
#pragma unroll
    for (int mt = 0; mt < 4; mt++)
        aOff[mt] = (uint32_t)((warpM + mt * 16 + (lane & 15)) * 80 + (lane >> 4) * 16);
    // B (x4, one per nt-pair): l0-7 rows n..n+7 k-lo, l8-15 k-hi, l16-23 rows+8 k-lo, l24-31 k-hi
    uint32_t bOff[2];
#pragma unroll
    for (int np = 0; np < 2; np++)
        bOff[np] = (uint32_t)(10240 +
                   (warpN + np * 16 + (lane & 7) + ((lane & 16) ? 8 : 0)) * 80 +
                   ((lane >> 3) & 1) * 16);

    float acc[4][4][4];
#pragma unroll
    for (int mt = 0; mt < 4; mt++)
#pragma unroll
        for (int nt = 0; nt < 4; nt++)
#pragma unroll
            for (int i = 0; i < 4; i++) acc[mt][nt][i] = 0.f;

    const int nStages = K >> 5;

    auto issue = [&](int buf, int ks) {
        uint32_t sA = sbase + buf * STAGE_BYTES;
        uint32_t sB = sA + 10240;
        int k0 = ks << 5;
#pragma unroll
        for (int i = 0; i < 2; i++) {
            int row = lrow + i * 64;
            int ar = m0 + row; if (ar >= M) ar = M - 1;
            cp16(sA + row * 80 + lq * 16, A + (size_t)ar * K + k0 + lq * 8);
            cp16(sB + row * 80 + lq * 16, B + (size_t)(n0 + row) * K + k0 + lq * 8);
        }
        asm volatile("cp.async.commit_group;");
    };

    issue(0, 0);
    if (nStages > 1) issue(1, 1);

    for (int ks = 0; ks < nStages; ks++) {
        if (ks + 1 < nStages)
            asm volatile("cp.async.wait_group 1;");
        else
            asm volatile("cp.async.wait_group 0;");
        __syncthreads();

        const uint32_t stage = sbase + (ks % 3) * STAGE_BYTES;

#pragma unroll
        for (int kk = 0; kk < 32; kk += 16) {
            const uint32_t kb = (kk >> 1) * 4;     // byte offset of k-chunk
            uint32_t a[4][4], b[2][4];
#pragma unroll
            for (int mt = 0; mt < 4; mt++)
                ldsm4(a[mt], stage + aOff[mt] + kb);
#pragma unroll
            for (int np = 0; np < 2; np++)
                ldsm4(b[np], stage + bOff[np] + kb);
#pragma unroll
            for (int mt = 0; mt < 4; mt++) {
                mma_bf16(acc[mt][0], a[mt], &b[0][0]);
                mma_bf16(acc[mt][1], a[mt], &b[0][2]);
                mma_bf16(acc[mt][2], a[mt], &b[1][0]);
                mma_bf16(acc[mt][3], a[mt], &b[1][2]);
            }
        }

        if (ks + 2 < nStages) issue((ks + 2) % 3, ks + 2);
    }

#pragma unroll
    for (int mt = 0; mt < 4; mt++) {
        int row0 = m0 + warpM + mt * 16 + g;
        int row1 = row0 + 8;
#pragma unroll
        for (int nt = 0; nt < 4; nt++) {
            int col = n0 + warpN + nt * 8 + tg * 2;
            float bx0 = bi[col], bx1 = bi[col + 1];
            float v0 = acc[mt][nt][0] + bx0;
            float v1 = acc[mt][nt][1] + bx1;
            float v2 = acc[mt][nt][2] + bx0;
            float v3 = acc[mt][nt][3] + bx1;
            if (doElu) {
                v0 = v0 > 0.f ? v0 : expm1f(v0);
                v1 = v1 > 0.f ? v1 : expm1f(v1);
                v2 = v2 > 0.f ? v2 : expm1f(v2);
                v3 = v3 > 0.f ? v3 : expm1f(v3);
            }
            if (Cb != nullptr) {
                if (row0 < M)
                    *(__nv_bfloat162*)(Cb + (size_t)row0 * N + col) =
                        __nv_bfloat162(__float2bfloat16(v0), __float2bfloat16(v1));
                if (row1 < M)
                    *(__nv_bfloat162*)(Cb + (size_t)row1 * N + col) =
                        __nv_bfloat162(__float2bfloat16(v2), __float2bfloat16(v3));
            } else {
                if (row0 < M) *(float2*)(C + (size_t)row0 * N + col) = make_float2(v0, v1);
                if (row1 < M) *(float2*)(C + (size_t)row1 * N + col) = make_float2(v2, v3);
            }
        }
    }
}

// ---------------- fused edge kernel: single pass ----------------------------
// softmax linearity: out = (sum_e ex_e * xl[src_e]) / denom.
// writeH: also emit fp32 h (only needed after the last conv layer).
__global__ void __launch_bounds__(256)
edge_fused(const float* __restrict__ We, const float* __restrict__ att,
           const float* __restrict__ bias, int writeH)
{
    __shared__ float4 sWe[HID / 4];
    __shared__ float4 sAtt[HID / 4];

    for (int i = threadIdx.x; i < HID / 4; i += blockDim.x) {
        sWe[i]  = ((const float4*)We)[i];
        sAtt[i] = ((const float4*)att)[i];
    }
    __syncthreads();

    const int wid  = threadIdx.x >> 5;
    const int lane = threadIdx.x & 31;
    const int node = blockIdx.x * 8 + wid;
    if (node >= NN) return;

    const int st = g_offs[node], en = g_offs[node + 1];

    float4 xr4[4];
    {
        const float4* xrp = (const float4*)(g_xr + (size_t)node * HID) + lane * 4;
#pragma unroll
        for (int q = 0; q < 4; q++) xr4[q] = xrp[q];
    }
    float4 we4[4], at4[4];
#pragma unroll
    for (int q = 0; q < 4; q++) { we4[q] = sWe[lane * 4 + q]; at4[q] = sAtt[lane * 4 + q]; }

    float denom = 0.f;
    float4 acc[4];
#pragma unroll
    for (int q = 0; q < 4; q++) acc[q] = make_float4(0.f, 0.f, 0.f, 0.f);

    // software pipeline: prefetch next edge's (src, dist)
    int   sNext = g_csrc[st];
    float dNext = g_cdist[st];
    for (int j = st; j < en; j++) {
        const int s = sNext;
        const float dv = dNext;
        const float4* xls = (const float4*)(g_xl + (size_t)s * HID) + lane * 4;
        float4 a0 = xls[0], a1 = xls[1], a2 = xls[2], a3 = xls[3];
        if (j + 1 < en) { sNext = g_csrc[j + 1]; dNext = g_cdist[j + 1]; }

        float partial = 0.f;
        {
            float v;
            float4 b = xr4[0], w = we4[0], t = at4[0];
            v = a0.x + b.x + dv * w.x; v = v > 0.f ? v : 0.2f * v; partial += v * t.x;
            v = a0.y + b.y + dv * w.y; v = v > 0.f ? v : 0.2f * v; partial += v * t.y;
            v = a0.z + b.z + dv * w.z; v = v > 0.f ? v : 0.2f * v; partial += v * t.z;
            v = a0.w + b.w + dv * w.w; v = v > 0.f ? v : 0.2f * v; partial += v * t.w;
            b = xr4[1]; w = we4[1]; t = at4[1];
            v = a1.x + b.x + dv * w.x; v = v > 0.f ? v : 0.2f * v; partial += v * t.x;
            v = a1.y + b.y + dv * w.y; v = v > 0.f ? v : 0.2f * v; partial += v * t.y;
            v = a1.z + b.z + dv * w.z; v = v > 0.f ? v : 0.2f * v; partial += v * t.z;
            v = a1.w + b.w + dv * w.w; v = v > 0.f ? v : 0.2f * v; partial += v * t.w;
            b = xr4[2]; w = we4[2]; t = at4[2];
            v = a2.x + b.x + dv * w.x; v = v > 0.f ? v : 0.2f * v; partial += v * t.x;
            v = a2.y + b.y + dv * w.y; v = v > 0.f ? v : 0.2f * v; partial += v * t.y;
            v = a2.z + b.z + dv * w.z; v = v > 0.f ? v : 0.2f * v; partial += v * t.z;
            v = a2.w + b.w + dv * w.w; v = v > 0.f ? v : 0.2f * v; partial += v * t.w;
            b = xr4[3]; w = we4[3]; t = at4[3];
            v = a3.x + b.x + dv * w.x; v = v > 0.f ? v : 0.2f * v; partial += v * t.x;
            v = a3.y + b.y + dv * w.y; v = v > 0.f ? v : 0.2f * v; partial += v * t.y;
            v = a3.z + b.z + dv * w.z; v = v > 0.f ? v : 0.2f * v; partial += v * t.z;
            v = a3.w + b.w + dv * w.w; v = v > 0.f ? v : 0.2f * v; partial += v * t.w;
        }
        partial += __shfl_xor_sync(0xffffffffu, partial, 1);
        partial += __shfl_xor_sync(0xffffffffu, partial, 2);
        float ex = expf(partial);   // softmax shift-invariant; scores O(1)
        denom += ex;
        acc[0].x += ex * a0.x; acc[0].y += ex * a0.y; acc[0].z += ex * a0.z; acc[0].w += ex * a0.w;
        acc[1].x += ex * a1.x; acc[1].y += ex * a1.y; acc[1].z += ex * a1.z; acc[1].w += ex * a1.w;
        acc[2].x += ex * a2.x; acc[2].y += ex * a2.y; acc[2].z += ex * a2.z; acc[2].w += ex * a2.w;
        acc[3].x += ex * a3.x; acc[3].y += ex * a3.y; acc[3].z += ex * a3.z; acc[3].w += ex * a3.w;
    }

    const float inv = 1.f / denom;      // self-loop => denom > 0

    const float4* b4 = (const float4*)bias + lane * 4;
    float* hp  = g_h  + (size_t)node * HID + lane * 16;
    bf16*  hbp = g_hb + (size_t)node * HID + lane * 16;
#pragma unroll
    for (int q = 0; q < 4; q++) {
        float4 b = b4[q];
        float4 v = acc[q];
        v.x = v.x * inv + b.x; v.y = v.y * inv + b.y;
        v.z = v.z * inv + b.z; v.w = v.w * inv + b.w;
        v.x = v.x > 0.f ? v.x : expm1f(v.x);
        v.y = v.y > 0.f ? v.y : expm1f(v.y);
        v.z = v.z > 0.f ? v.z : expm1f(v.z);
        v.w = v.w > 0.f ? v.w : expm1f(v.w);
        if (writeH) *(float4*)(hp + q * 4) = v;
        __nv_bfloat162 p0(__float2bfloat16(v.x), __float2bfloat16(v.y));
        __nv_bfloat162 p1(__float2bfloat16(v.z), __float2bfloat16(v.w));
        *(__nv_bfloat162*)(hbp + q * 4)     = p0;
        *(__nv_bfloat162*)(hbp + q * 4 + 2) = p1;
    }
}

// ---------------- final: logits = h @ Wa + ba; log_softmax -------------------
__global__ void final_kernel(const float* __restrict__ Wa,
                             const float* __restrict__ ba,
                             float* __restrict__ out)
{
    const int row = blockIdx.x * (blockDim.x >> 5) + (threadIdx.x >> 5);
    const int lane = threadIdx.x & 31;
    if (row >= NN) return;

    const float* hrow = g_h + (size_t)row * HID;
    float acc[NCLS];
#pragma unroll
    for (int c = 0; c < NCLS; c++) acc[c] = 0.f;

    for (int k = lane; k < HID; k += 32) {
        float hv = hrow[k];
        const float* wrow = Wa + (size_t)k * NCLS;
#pragma unroll
        for (int c = 0; c < NCLS; c++) acc[c] += hv * wrow[c];
    }
#pragma unroll
    for (int off = 16; off > 0; off >>= 1)
#pragma unroll
        for (int c = 0; c < NCLS; c++)
            acc[c] += __shfl_xor_sync(0xffffffffu, acc[c], off);

    if (lane == 0) {
        float z[NCLS], mx = -1e30f;
#pragma unroll
        for (int c = 0; c < NCLS; c++) { z[c] = acc[c] + ba[c]; mx = fmaxf(mx, z[c]); }
        float s = 0.f;
#pragma unroll
        for (int c = 0; c < NCLS; c++) s += expf(z[c] - mx);
        float lse = mx + logf(s);
#pragma unroll
        for (int c = 0; c < NCLS; c++) out[(size_t)row * NCLS + c] = z[c] - lse;
    }
}

// ---------------- launch ----------------
extern "C" void kernel_launch(void* const* d_in, const int* in_sizes, int n_in,
                              void* d_out, int out_size)
{
    const float* x    = (const float*)d_in[0];
    const int*   ei   = (const int*)d_in[1];      // int32 (JAX x64 disabled)
    const float* dist = (const float*)d_in[2];
    const float* Wb   = (const float*)d_in[3];
    const float* bb   = (const float*)d_in[4];
    const float* Wl   = (const float*)d_in[5];
    const float* bl   = (const float*)d_in[6];
    const float* Wr   = (const float*)d_in[7];
    const float* br   = (const float*)d_in[8];
    const float* We   = (const float*)d_in[9];
    const float* att  = (const float*)d_in[10];
    const float* bc   = (const float*)d_in[11];
    const float* Wa   = (const float*)d_in[12];
    const float* ba   = (const float*)d_in[13];
    float* out = (float*)d_out;

    float *pxl, *pxr;
    bf16 *phb, *pxb, *pwbT, *pwlT, *pwrT;
    int *pcnt, *poffs, *pcur;
    cudaGetSymbolAddress((void**)&pxl,  g_xl);
    cudaGetSymbolAddress((void**)&pxr,  g_xr);
    cudaGetSymbolAddress((void**)&phb,  g_hb);
    cudaGetSymbolAddress((void**)&pxb,  g_xb);
    cudaGetSymbolAddress((void**)&pwbT, g_wbT);
    cudaGetSymbolAddress((void**)&pwlT, g_wlT);
    cudaGetSymbolAddress((void**)&pwrT, g_wrT);
    cudaGetSymbolAddress((void**)&pcnt, g_cnt);
    cudaGetSymbolAddress((void**)&poffs, g_offs);
    cudaGetSymbolAddress((void**)&pcur, g_cursor);

    cudaFuncSetAttribute(bf16gemm, cudaFuncAttributeMaxDynamicSharedMemorySize, GEMM_SMEM);

    // ---- prep ----
    conv_x_kernel<<<(NN * FIN + 255) / 256, 256>>>(x);                      // 1
    dim3 tb(32, 8);
    transp_bf16<<<dim3(HID / 32, FIN / 32), tb>>>(Wb, pwbT, FIN, HID);      // 2
    transp_bf16_batch6<<<dim3(HID / 32, HID / 32, 6), tb>>>(Wl, Wr);        // 3
    zero_i<<<(NN + 255) / 256, 256>>>(pcnt, NN);                            // 4
    hist_kernel<<<(ETOT + 255) / 256, 256>>>(ei);                           // 5
    // fcnn_before: hb = bf16(elu(x @ Wb + bb))                              // 6
    bf16gemm<<<dim3(HID / 128, (NN + 127) / 128), 256, GEMM_SMEM>>>(
        pxb, pwbT, nullptr, bb, nullptr, nullptr, nullptr, phb, NN, FIN, 1);
    scan_kernel<<<1, 1024>>>();                                             // 7
    copy_i<<<(NN + 255) / 256, 256>>>(poffs, pcur, NN);                     // 8
    scatter_kernel<<<(ETOT + 255) / 256, 256>>>(ei, dist);                  // 9

    for (int i = 0; i < 3; i++) {
        // fused dual GEMM: xl = hb @ Wl^T + bl ; xr = hb @ Wr^T + br (fp32 out)
        bf16gemm<<<dim3(2 * HID / 128, (NN + 127) / 128), 256, GEMM_SMEM>>>(
            phb, pwlT + (size_t)i * HID * HID, pwrT + (size_t)i * HID * HID,
            bl + i * HID, br + i * HID, pxl, pxr, nullptr, NN, HID, 0);
        edge_fused<<<(NN + 7) / 8, 256>>>(We + (size_t)i * HID,
                                          att + (size_t)i * HID,
                                          bc + (size_t)i * HID, i == 2);
    }

    final_kernel<<<(NN + 7) / 8, 256>>>(Wa, ba, out);
}

// round 11
// speedup vs baseline: 7.5436x; 1.0725x over previous
#include <cuda_runtime.h>
#include <cuda_bf16.h>
#include <math.h>
#include <stdint.h>

typedef __nv_bfloat16 bf16;

#define NN   10000
#define EE   160000
#define ETOT 170000   // EE + NN self loops
#define FIN  128
#define HID  512
#define HH   8
#define CC   64
#define NCLS 10
#define CAP  128      // per-node in-edge bucket capacity (P(overflow) ~ 1e-60)

// ---------------- scratch (device globals; no allocs allowed) ----------------
__device__ float g_h [NN * HID];          // fp32 h (final layer only)
__device__ bf16  g_hb[NN * HID];          // bf16 h (GEMM A input)
__device__ bf16  g_xb[NN * FIN];          // bf16 x
__device__ bf16  g_xlb[NN * HID];         // bf16 xl
__device__ bf16  g_xrb[NN * HID];         // bf16 xr
__device__ bf16  g_wbT[HID * FIN];        // Wb^T  [n][k]
__device__ bf16  g_wlT[3 * HID * HID];    // Wl^T per layer
__device__ bf16  g_wrT[3 * HID * HID];    // Wr^T per layer
__device__ int   g_cnt[NN];
__device__ int   g_bsrc[(size_t)NN * CAP];
__device__ float g_bdist[(size_t)NN * CAP];

// ---------------- small helpers ----------------
__global__ void zero_i(int* __restrict__ p, int n)
{
    int i = blockIdx.x * blockDim.x + threadIdx.x;
    if (i < n) p[i] = 0;
}
__global__ void conv_x_kernel(const float* __restrict__ x)
{
    int i = blockIdx.x * blockDim.x + threadIdx.x;
    if (i < NN * FIN) g_xb[i] = __float2bfloat16(x[i]);
}

// transpose+convert: dst[n][k] = bf16(src[k][n]); K,N multiples of 32
__global__ void transp_bf16(const float* __restrict__ src, bf16* __restrict__ dst,
                            int K, int N)
{
    __shared__ float tile[32][33];
    int k0 = blockIdx.y * 32, n0 = blockIdx.x * 32;
    int tx = threadIdx.x, ty = threadIdx.y;   // 32 x 8
#pragma unroll
    for (int i = 0; i < 32; i += 8)
        tile[ty + i][tx] = src[(size_t)(k0 + ty + i) * N + n0 + tx];
    __syncthreads();
#pragma unroll
    for (int i = 0; i < 32; i += 8)
        dst[(size_t)(n0 + ty + i) * K + k0 + tx] = __float2bfloat16(tile[tx][ty + i]);
}

// batched version for the six HID x HID weight matrices (Wl 0..2, Wr 0..2)
__global__ void transp_bf16_batch6(const float* __restrict__ Wl,
                                   const float* __restrict__ Wr)
{
    __shared__ float tile[32][33];
    int z = blockIdx.z;
    const float* src = (z < 3) ? Wl + (size_t)z * HID * HID
                               : Wr + (size_t)(z - 3) * HID * HID;
    bf16* dst = (z < 3) ? g_wlT + (size_t)z * HID * HID
                        : g_wrT + (size_t)(z - 3) * HID * HID;
    int k0 = blockIdx.y * 32, n0 = blockIdx.x * 32;
    int tx = threadIdx.x, ty = threadIdx.y;
#pragma unroll
    for (int i = 0; i < 32; i += 8)
        tile[ty + i][tx] = src[(size_t)(k0 + ty + i) * HID + n0 + tx];
    __syncthreads();
#pragma unroll
    for (int i = 0; i < 32; i += 8)
        dst[(size_t)(n0 + ty + i) * HID + k0 + tx] = __float2bfloat16(tile[tx][ty + i]);
}

// ---------------- bucket build (replaces CSR hist/scan/scatter) -------------
__global__ void bucket_kernel(const int* __restrict__ ei,
                              const float* __restrict__ dist)
{
    int e = blockIdx.x * blockDim.x + threadIdx.x;
    if (e >= ETOT) return;
    int s, d; float dv;
    if (e < EE) { s = ei[e]; d = ei[EE + e]; dv = dist[e]; }
    else        { s = d = e - EE; dv = 0.f; }
    int pos = atomicAdd(&g_cnt[d], 1);
    if (pos < CAP) {
        g_bsrc [(size_t)d * CAP + pos] = s;
        g_bdist[(size_t)d * CAP + pos] = dv;
    }
}

// ---------------- bf16 tensor-core GEMM -------------------------------------
// Cb[M,N] = bf16(A[M,K] @ B^T + bias [elu]), B stored [N][K] bf16.
// 128x128 tile, 256 thr, K-chunk 32, 4-stage cp.async ring, ldmatrix frags.
__device__ __forceinline__ void mma_bf16(float* c, const uint32_t* a, const uint32_t* b)
{
    asm volatile(
        "mma.sync.aligned.m16n8k16.row.col.f32.bf16.bf16.f32 "
        "{%0,%1,%2,%3}, {%4,%5,%6,%7}, {%8,%9}, {%0,%1,%2,%3};"
        : "+f"(c[0]), "+f"(c[1]), "+f"(c[2]), "+f"(c[3])
        : "r"(a[0]), "r"(a[1]), "r"(a[2]), "r"(a[3]), "r"(b[0]), "r"(b[1]));
}
__device__ __forceinline__ void cp16(uint32_t dst, const void* src)
{
    asm volatile("cp.async.cg.shared.global [%0], [%1], 16;" :: "r"(dst), "l"(src));
}
__device__ __forceinline__ void ldsm4(uint32_t* r, uint32_t addr)
{
    asm volatile("ldmatrix.sync.aligned.m8n8.x4.shared.b16 {%0,%1,%2,%3}, [%4];"
                 : "=r"(r[0]), "=r"(r[1]), "=r"(r[2]), "=r"(r[3]) : "r"(addr));
}

#define STAGE_BYTES 20480                  // A: 128*80 + B: 128*80
#define GEMM_SMEM   (4 * STAGE_BYTES)      // 81920, dynamic (occ 2: 160KB/SM)

__global__ void __launch_bounds__(256, 2)
bf16gemm(const bf16* __restrict__ A,
         const bf16* __restrict__ B0, const bf16* __restrict__ B1,
         const float* __restrict__ bias0, const float* __restrict__ bias1,
         bf16* __restrict__ Cb0, bf16* __restrict__ Cb1,
         int M, int K, int doElu)
{
    extern __shared__ __align__(16) unsigned char smem[];
    const int N = HID;

    const int tid  = threadIdx.x;
    const int wid  = tid >> 5;
    const int lane = tid & 31;
    const int g    = lane >> 2;
    const int tg   = lane & 3;

    const bf16* B = B0;
    bf16* Cb = Cb0;
    const float* bi = bias0;
    int bx = blockIdx.x;
    if (B1 != nullptr && bx >= ((int)gridDim.x >> 1)) {
        B = B1; Cb = Cb1; bi = bias1; bx -= (int)gridDim.x >> 1;
    }
    const int m0 = blockIdx.y * 128;
    const int n0 = bx * 128;
    const int warpM = (wid >> 2) * 64;
    const int warpN = (wid & 3) * 32;

    const uint32_t sbase = (uint32_t)__cvta_generic_to_shared(smem);

    const int lrow = tid >> 2;          // cp.async row for i=0; i adds 64
    const int lq   = tid & 3;

    // ldmatrix per-lane address offsets (within a stage buffer)
    uint32_t aOff[4];
#pragma unroll
    for (int mt = 0; mt < 4; mt++)
        aOff[mt] = (uint32_t)((warpM + mt * 16 + (lane & 15)) * 80 + (lane >> 4) * 16);
    uint32_t bOff[2];
#pragma unroll
    for (int np = 0; np < 2; np++)
        bOff[np] = (uint32_t)(10240 +
                   (warpN + np * 16 + (lane & 7) + ((lane & 16) ? 8 : 0)) * 80 +
                   ((lane >> 3) & 1) * 16);

    float acc[4][4][4];
#pragma unroll
    for (int mt = 0; mt < 4; mt++)
#pragma unroll
        for (int nt = 0; nt < 4; nt++)
#pragma unroll
            for (int i = 0; i < 4; i++) acc[mt][nt][i] = 0.f;

    const int nStages = K >> 5;

    auto issue = [&](int buf, int ks) {
        uint32_t sA = sbase + buf * STAGE_BYTES;
        uint32_t sB = sA + 10240;
        int k0 = ks << 5;
#pragma unroll
        for (int i = 0; i < 2; i++) {
            int row = lrow + i * 64;
            int ar = m0 + row; if (ar >= M) ar = M - 1;
            cp16(sA + row * 80 + lq * 16, A + (size_t)ar * K + k0 + lq * 8);
            cp16(sB + row * 80 + lq * 16, B + (size_t)(n0 + row) * K + k0 + lq * 8);
        }
        asm volatile("cp.async.commit_group;");
    };

    issue(0, 0);
    if (nStages > 1) issue(1, 1);
    if (nStages > 2) issue(2, 2);

    for (int ks = 0; ks < nStages; ks++) {
        int rem = nStages - 1 - ks;
        if (rem >= 2)      asm volatile("cp.async.wait_group 2;");
        else if (rem == 1) asm volatile("cp.async.wait_group 1;");
        else               asm volatile("cp.async.wait_group 0;");
        __syncthreads();

        const uint32_t stage = sbase + (ks & 3) * STAGE_BYTES;

#pragma unroll
        for (int kk = 0; kk < 32; kk += 16) {
            const uint32_t kb = (kk >> 1) * 4;
            uint32_t a[4][4], b[2][4];
#pragma unroll
            for (int mt = 0; mt < 4; mt++)
                ldsm4(a[mt], stage + aOff[mt] + kb);
#pragma unroll
            for (int np = 0; np < 2; np++)
                ldsm4(b[np], stage + bOff[np] + kb);
#pragma unroll
            for (int mt = 0; mt < 4; mt++) {
                mma_bf16(acc[mt][0], a[mt], &b[0][0]);
                mma_bf16(acc[mt][1], a[mt], &b[0][2]);
                mma_bf16(acc[mt][2], a[mt], &b[1][0]);
                mma_bf16(acc[mt][3], a[mt], &b[1][2]);
            }
        }

        if (ks + 4 < nStages + 1 && ks + 3 < nStages) issue((ks + 3) & 3, ks + 3);
    }

#pragma unroll
    for (int mt = 0; mt < 4; mt++) {
        int row0 = m0 + warpM + mt * 16 + g;
        int row1 = row0 + 8;
#pragma unroll
        for (int nt = 0; nt < 4; nt++) {
            int col = n0 + warpN + nt * 8 + tg * 2;
            float bx0 = bi[col], bx1 = bi[col + 1];
            float v0 = acc[mt][nt][0] + bx0;
            float v1 = acc[mt][nt][1] + bx1;
            float v2 = acc[mt][nt][2] + bx0;
            float v3 = acc[mt][nt][3] + bx1;
            if (doElu) {
                v0 = v0 > 0.f ? v0 : expm1f(v0);
                v1 = v1 > 0.f ? v1 : expm1f(v1);
                v2 = v2 > 0.f ? v2 : expm1f(v2);
                v3 = v3 > 0.f ? v3 : expm1f(v3);
            }
            if (row0 < M)
                *(__nv_bfloat162*)(Cb + (size_t)row0 * N + col) =
                    __nv_bfloat162(__float2bfloat16(v0), __float2bfloat16(v1));
            if (row1 < M)
                *(__nv_bfloat162*)(Cb + (size_t)row1 * N + col) =
                    __nv_bfloat162(__float2bfloat16(v2), __float2bfloat16(v3));
        }
    }
}

// ---------------- fused edge kernel: single pass, bf16 features -------------
// out = (sum_e ex_e * xl[src_e]) / denom ; warp per node, bucket in-edges.
__global__ void __launch_bounds__(256)
edge_fused(const float* __restrict__ We, const float* __restrict__ att,
           const float* __restrict__ bias, int writeH)
{
    __shared__ float4 sWe[HID / 4];
    __shared__ float4 sAtt[HID / 4];

    for (int i = threadIdx.x; i < HID / 4; i += blockDim.x) {
        sWe[i]  = ((const float4*)We)[i];
        sAtt[i] = ((const float4*)att)[i];
    }
    __syncthreads();

    const int wid  = threadIdx.x >> 5;
    const int lane = threadIdx.x & 31;
    const int node = blockIdx.x * 8 + wid;
    if (node >= NN) return;

    int deg = g_cnt[node];
    if (deg > CAP) deg = CAP;
    const int*   bsrc  = g_bsrc  + (size_t)node * CAP;
    const float* bdist = g_bdist + (size_t)node * CAP;

    // xr[node] slice: 16 channels per lane (bf16 -> fp32 registers)
    float xr[16];
    {
        const uint4* xrp = (const uint4*)(g_xrb + (size_t)node * HID + lane * 16);
        uint4 p0 = xrp[0], p1 = xrp[1];
        const __nv_bfloat162* h0 = (const __nv_bfloat162*)&p0;
        const __nv_bfloat162* h1 = (const __nv_bfloat162*)&p1;
#pragma unroll
        for (int q = 0; q < 4; q++) {
            float2 f0 = __bfloat1622float2(h0[q]);
            float2 f1 = __bfloat1622float2(h1[q]);
            xr[q * 2 + 0] = f0.x; xr[q * 2 + 1] = f0.y;
            xr[8 + q * 2 + 0] = f1.x; xr[8 + q * 2 + 1] = f1.y;
        }
    }
    float we[16], at[16];
#pragma unroll
    for (int q = 0; q < 4; q++) {
        float4 w = sWe[lane * 4 + q], t = sAtt[lane * 4 + q];
        we[q * 4 + 0] = w.x; we[q * 4 + 1] = w.y; we[q * 4 + 2] = w.z; we[q * 4 + 3] = w.w;
        at[q * 4 + 0] = t.x; at[q * 4 + 1] = t.y; at[q * 4 + 2] = t.z; at[q * 4 + 3] = t.w;
    }
    // NOTE: xr loaded pairwise (q*2 layout) — build matching index map for we/at:
    // xr[i] above is stored as [p0 pairs 0..7 = ch 0..7][p1 pairs = ch 8..15],
    // which IS channels 0..15 in order. we/at are also ch 0..15 in order. OK.

    float denom = 0.f;
    float acc[16];
#pragma unroll
    for (int i = 0; i < 16; i++) acc[i] = 0.f;

    int   sNext = bsrc[0];
    float dNext = bdist[0];
    for (int j = 0; j < deg; j++) {
        const int s = sNext;
        const float dv = dNext;
        const uint4* xlp = (const uint4*)(g_xlb + (size_t)s * HID + lane * 16);
        uint4 p0 = xlp[0], p1 = xlp[1];
        if (j + 1 < deg) { sNext = bsrc[j + 1]; dNext = bdist[j + 1]; }

        float a[16];
        {
            const __nv_bfloat162* h0 = (const __nv_bfloat162*)&p0;
            const __nv_bfloat162* h1 = (const __nv_bfloat162*)&p1;
#pragma unroll
            for (int q = 0; q < 4; q++) {
                float2 f0 = __bfloat1622float2(h0[q]);
                float2 f1 = __bfloat1622float2(h1[q]);
                a[q * 2 + 0] = f0.x; a[q * 2 + 1] = f0.y;
                a[8 + q * 2 + 0] = f1.x; a[8 + q * 2 + 1] = f1.y;
            }
        }

        float partial = 0.f;
#pragma unroll
        for (int i = 0; i < 16; i++) {
            float v = a[i] + xr[i] + dv * we[i];
            v = v > 0.f ? v : 0.2f * v;
            partial += v * at[i];
        }
        partial += __shfl_xor_sync(0xffffffffu, partial, 1);
        partial += __shfl_xor_sync(0xffffffffu, partial, 2);
        float ex = expf(partial);   // softmax shift-invariant; scores O(1)
        denom += ex;
#pragma unroll
        for (int i = 0; i < 16; i++) acc[i] += ex * a[i];
    }

    const float inv = 1.f / denom;      // self-loop => denom > 0

    const float* bp = bias + lane * 16;
    float* hp  = g_h  + (size_t)node * HID + lane * 16;
    bf16*  hbp = g_hb + (size_t)node * HID + lane * 16;
#pragma unroll
    for (int i = 0; i < 16; i += 2) {
        float v0 = acc[i] * inv + bp[i];
        float v1 = acc[i + 1] * inv + bp[i + 1];
        v0 = v0 > 0.f ? v0 : expm1f(v0);
        v1 = v1 > 0.f ? v1 : expm1f(v1);
        if (writeH) { hp[i] = v0; hp[i + 1] = v1; }
        *(__nv_bfloat162*)(hbp + i) =
            __nv_bfloat162(__float2bfloat16(v0), __float2bfloat16(v1));
    }
}

// ---------------- final: logits = h @ Wa + ba; log_softmax -------------------
__global__ void final_kernel(const float* __restrict__ Wa,
                             const float* __restrict__ ba,
                             float* __restrict__ out)
{
    const int row = blockIdx.x * (blockDim.x >> 5) + (threadIdx.x >> 5);
    const int lane = threadIdx.x & 31;
    if (row >= NN) return;

    const float* hrow = g_h + (size_t)row * HID;
    float acc[NCLS];
#pragma unroll
    for (int c = 0; c < NCLS; c++) acc[c] = 0.f;

    for (int k = lane; k < HID; k += 32) {
        float hv = hrow[k];
        const float* wrow = Wa + (size_t)k * NCLS;
#pragma unroll
        for (int c = 0; c < NCLS; c++) acc[c] += hv * wrow[c];
    }
#pragma unroll
    for (int off = 16; off > 0; off >>= 1)
#pragma unroll
        for (int c = 0; c < NCLS; c++)
            acc[c] += __shfl_xor_sync(0xffffffffu, acc[c], off);

    if (lane == 0) {
        float z[NCLS], mx = -1e30f;
#pragma unroll
        for (int c = 0; c < NCLS; c++) { z[c] = acc[c] + ba[c]; mx = fmaxf(mx, z[c]); }
        float s = 0.f;
#pragma unroll
        for (int c = 0; c < NCLS; c++) s += expf(z[c] - mx);
        float lse = mx + logf(s);
#pragma unroll
        for (int c = 0; c < NCLS; c++) out[(size_t)row * NCLS + c] = z[c] - lse;
    }
}

// ---------------- launch ----------------
extern "C" void kernel_launch(void* const* d_in, const int* in_sizes, int n_in,
                              void* d_out, int out_size)
{
    const float* x    = (const float*)d_in[0];
    const int*   ei   = (const int*)d_in[1];      // int32 (JAX x64 disabled)
    const float* dist = (const float*)d_in[2];
    const float* Wb   = (const float*)d_in[3];
    const float* bb   = (const float*)d_in[4];
    const float* Wl   = (const float*)d_in[5];
    const float* bl   = (const float*)d_in[6];
    const float* Wr   = (const float*)d_in[7];
    const float* br   = (const float*)d_in[8];
    const float* We   = (const float*)d_in[9];
    const float* att  = (const float*)d_in[10];
    const float* bc   = (const float*)d_in[11];
    const float* Wa   = (const float*)d_in[12];
    const float* ba   = (const float*)d_in[13];
    float* out = (float*)d_out;

    bf16 *phb, *pxb, *pxlb, *pxrb, *pwbT, *pwlT, *pwrT;
    int *pcnt;
    cudaGetSymbolAddress((void**)&phb,  g_hb);
    cudaGetSymbolAddress((void**)&pxb,  g_xb);
    cudaGetSymbolAddress((void**)&pxlb, g_xlb);
    cudaGetSymbolAddress((void**)&pxrb, g_xrb);
    cudaGetSymbolAddress((void**)&pwbT, g_wbT);
    cudaGetSymbolAddress((void**)&pwlT, g_wlT);
    cudaGetSymbolAddress((void**)&pwrT, g_wrT);
    cudaGetSymbolAddress((void**)&pcnt, g_cnt);

    cudaFuncSetAttribute(bf16gemm, cudaFuncAttributeMaxDynamicSharedMemorySize, GEMM_SMEM);

    // ---- prep ----
    conv_x_kernel<<<(NN * FIN + 255) / 256, 256>>>(x);
    dim3 tb(32, 8);
    transp_bf16<<<dim3(HID / 32, FIN / 32), tb>>>(Wb, pwbT, FIN, HID);
    transp_bf16_batch6<<<dim3(HID / 32, HID / 32, 6), tb>>>(Wl, Wr);
    zero_i<<<(NN + 255) / 256, 256>>>(pcnt, NN);
    bucket_kernel<<<(ETOT + 255) / 256, 256>>>(ei, dist);

    // fcnn_before: hb = bf16(elu(x @ Wb + bb))
    bf16gemm<<<dim3(HID / 128, (NN + 127) / 128), 256, GEMM_SMEM>>>(
        pxb, pwbT, nullptr, bb, nullptr, phb, nullptr, NN, FIN, 1);

    for (int i = 0; i < 3; i++) {
        // fused dual GEMM: xlb = hb @ Wl^T + bl ; xrb = hb @ Wr^T + br (bf16)
        bf16gemm<<<dim3(2 * HID / 128, (NN + 127) / 128), 256, GEMM_SMEM>>>(
            phb, pwlT + (size_t)i * HID * HID, pwrT + (size_t)i * HID * HID,
            bl + i * HID, br + i * HID, pxlb, pxrb, NN, HID, 0);
        edge_fused<<<(NN + 7) / 8, 256>>>(We + (size_t)i * HID,
                                          att + (size_t)i * HID,
                                          bc + (size_t)i * HID, i == 2);
    }

    final_kernel<<<(NN + 7) / 8, 256>>>(Wa, ba, out);
}

// round 12
// speedup vs baseline: 7.9258x; 1.0507x over previous
#include <cuda_runtime.h>
#include <cuda_bf16.h>
#include <math.h>
#include <stdint.h>

typedef __nv_bfloat16 bf16;

#define NN   10000
#define EE   160000
#define ETOT 170000   // EE + NN self loops
#define FIN  128
#define HID  512
#define HH   8
#define CC   64
#define NCLS 10
#define CAP  128      // per-node in-edge bucket capacity (P(overflow) ~ 1e-60)

// ---------------- scratch (device globals; no allocs allowed) ----------------
__device__ bf16  g_hb[NN * HID];          // bf16 h (GEMM A input + final input)
__device__ bf16  g_xb[NN * FIN];          // bf16 x
__device__ bf16  g_xlb[NN * HID];         // bf16 xl
__device__ bf16  g_xrb[NN * HID];         // bf16 xr
__device__ bf16  g_wbT[HID * FIN];        // Wb^T  [n][k]
__device__ bf16  g_wlT[3 * HID * HID];    // Wl^T per layer
__device__ bf16  g_wrT[3 * HID * HID];    // Wr^T per layer
__device__ int   g_cnt[NN];
__device__ int   g_bsrc[(size_t)NN * CAP];
__device__ float g_bdist[(size_t)NN * CAP];

// ---------------- fused: convert x to bf16 AND zero g_cnt -------------------
__global__ void conv_x_zero(const float* __restrict__ x)
{
    int i = blockIdx.x * blockDim.x + threadIdx.x;
    if (i < NN * FIN) g_xb[i] = __float2bfloat16(x[i]);
    if (i < NN) g_cnt[i] = 0;
}

// batched transpose+convert for all 7 weight matrices:
// z=0..2: Wl[z] (512x512), z=3..5: Wr[z-3], z=6: Wb (128x512, y<4 only)
__global__ void transp_bf16_batch7(const float* __restrict__ Wl,
                                   const float* __restrict__ Wr,
                                   const float* __restrict__ Wb)
{
    __shared__ float tile[32][33];
    int z = blockIdx.z;
    const float* src;
    bf16* dst;
    int K;
    if (z < 3)      { src = Wl + (size_t)z * HID * HID;       dst = g_wlT + (size_t)z * HID * HID;       K = HID; }
    else if (z < 6) { src = Wr + (size_t)(z - 3) * HID * HID; dst = g_wrT + (size_t)(z - 3) * HID * HID; K = HID; }
    else            { src = Wb;                               dst = g_wbT;                               K = FIN;
                      if (blockIdx.y >= FIN / 32) return; }
    int k0 = blockIdx.y * 32, n0 = blockIdx.x * 32;
    int tx = threadIdx.x, ty = threadIdx.y;   // 32 x 8
#pragma unroll
    for (int i = 0; i < 32; i += 8)
        tile[ty + i][tx] = src[(size_t)(k0 + ty + i) * HID + n0 + tx];
    __syncthreads();
#pragma unroll
    for (int i = 0; i < 32; i += 8)
        dst[(size_t)(n0 + ty + i) * K + k0 + tx] = __float2bfloat16(tile[tx][ty + i]);
}

// ---------------- bucket build ----------------------------------------------
__global__ void bucket_kernel(const int* __restrict__ ei,
                              const float* __restrict__ dist)
{
    int e = blockIdx.x * blockDim.x + threadIdx.x;
    if (e >= ETOT) return;
    int s, d; float dv;
    if (e < EE) { s = ei[e]; d = ei[EE + e]; dv = dist[e]; }
    else        { s = d = e - EE; dv = 0.f; }
    int pos = atomicAdd(&g_cnt[d], 1);
    if (pos < CAP) {
        g_bsrc [(size_t)d * CAP + pos] = s;
        g_bdist[(size_t)d * CAP + pos] = dv;
    }
}

// ---------------- bf16 tensor-core GEMM -------------------------------------
// Cb[M,N] = bf16(A[M,K] @ B^T + bias [elu]), B stored [N][K] bf16.
// 128x128 tile, 256 thr, K-chunk 32, 4-stage cp.async ring, ldmatrix frags.
__device__ __forceinline__ void mma_bf16(float* c, const uint32_t* a, const uint32_t* b)
{
    asm volatile(
        "mma.sync.aligned.m16n8k16.row.col.f32.bf16.bf16.f32 "
        "{%0,%1,%2,%3}, {%4,%5,%6,%7}, {%8,%9}, {%0,%1,%2,%3};"
        : "+f"(c[0]), "+f"(c[1]), "+f"(c[2]), "+f"(c[3])
        : "r"(a[0]), "r"(a[1]), "r"(a[2]), "r"(a[3]), "r"(b[0]), "r"(b[1]));
}
__device__ __forceinline__ void cp16(uint32_t dst, const void* src)
{
    asm volatile("cp.async.cg.shared.global [%0], [%1], 16;" :: "r"(dst), "l"(src));
}
__device__ __forceinline__ void ldsm4(uint32_t* r, uint32_t addr)
{
    asm volatile("ldmatrix.sync.aligned.m8n8.x4.shared.b16 {%0,%1,%2,%3}, [%4];"
                 : "=r"(r[0]), "=r"(r[1]), "=r"(r[2]), "=r"(r[3]) : "r"(addr));
}

#define STAGE_BYTES 20480                  // A: 128*80 + B: 128*80
#define GEMM_SMEM   (4 * STAGE_BYTES)      // 81920, dynamic (occ 2: 160KB/SM)

__global__ void __launch_bounds__(256, 2)
bf16gemm(const bf16* __restrict__ A,
         const bf16* __restrict__ B0, const bf16* __restrict__ B1,
         const float* __restrict__ bias0, const float* __restrict__ bias1,
         bf16* __restrict__ Cb0, bf16* __restrict__ Cb1,
         int M, int K, int doElu)
{
    extern __shared__ __align__(16) unsigned char smem[];
    const int N = HID;

    const int tid  = threadIdx.x;
    const int wid  = tid >> 5;
    const int lane = tid & 31;
    const int g    = lane >> 2;
    const int tg   = lane & 3;

    const bf16* B = B0;
    bf16* Cb = Cb0;
    const float* bi = bias0;
    int bx = blockIdx.x;
    if (B1 != nullptr && bx >= ((int)gridDim.x >> 1)) {
        B = B1; Cb = Cb1; bi = bias1; bx -= (int)gridDim.x >> 1;
    }
    const int m0 = blockIdx.y * 128;
    const int n0 = bx * 128;
    const int warpM = (wid >> 2) * 64;
    const int warpN = (wid & 3) * 32;

    const uint32_t sbase = (uint32_t)__cvta_generic_to_shared(smem);

    const int lrow = tid >> 2;          // cp.async row for i=0; i adds 64
    const int lq   = tid & 3;

    uint32_t aOff[4];
#pragma unroll
    for (int mt = 0; mt < 4; mt++)
        aOff[mt] = (uint32_t)((warpM + mt * 16 + (lane & 15)) * 80 + (lane >> 4) * 16);
    uint32_t bOff[2];
#pragma unroll
    for (int np = 0; np < 2; np++)
        bOff[np] = (uint32_t)(10240 +
                   (warpN + np * 16 + (lane & 7) + ((lane & 16) ? 8 : 0)) * 80 +
                   ((lane >> 3) & 1) * 16);

    float acc[4][4][4];
#pragma unroll
    for (int mt = 0; mt < 4; mt++)
#pragma unroll
        for (int nt = 0; nt < 4; nt++)
#pragma unroll
            for (int i = 0; i < 4; i++) acc[mt][nt][i] = 0.f;

    const int nStages = K >> 5;

    auto issue = [&](int buf, int ks) {
        uint32_t sA = sbase + buf * STAGE_BYTES;
        uint32_t sB = sA + 10240;
        int k0 = ks << 5;
#pragma unroll
        for (int i = 0; i < 2; i++) {
            int row = lrow + i * 64;
            int ar = m0 + row; if (ar >= M) ar = M - 1;
            cp16(sA + row * 80 + lq * 16, A + (size_t)ar * K + k0 + lq * 8);
            cp16(sB + row * 80 + lq * 16, B + (size_t)(n0 + row) * K + k0 + lq * 8);
        }
        asm volatile("cp.async.commit_group;");
    };

    issue(0, 0);
    if (nStages > 1) issue(1, 1);
    if (nStages > 2) issue(2, 2);

    for (int ks = 0; ks < nStages; ks++) {
        int rem = nStages - 1 - ks;
        if (rem >= 2)      asm volatile("cp.async.wait_group 2;");
        else if (rem == 1) asm volatile("cp.async.wait_group 1;");
        else               asm volatile("cp.async.wait_group 0;");
        __syncthreads();

        const uint32_t stage = sbase + (ks & 3) * STAGE_BYTES;

#pragma unroll
        for (int kk = 0; kk < 32; kk += 16) {
            const uint32_t kb = (kk >> 1) * 4;
            uint32_t a[4][4], b[2][4];
#pragma unroll
            for (int mt = 0; mt < 4; mt++)
                ldsm4(a[mt], stage + aOff[mt] + kb);
#pragma unroll
            for (int np = 0; np < 2; np++)
                ldsm4(b[np], stage + bOff[np] + kb);
#pragma unroll
            for (int mt = 0; mt < 4; mt++) {
                mma_bf16(acc[mt][0], a[mt], &b[0][0]);
                mma_bf16(acc[mt][1], a[mt], &b[0][2]);
                mma_bf16(acc[mt][2], a[mt], &b[1][0]);
                mma_bf16(acc[mt][3], a[mt], &b[1][2]);
            }
        }

        if (ks + 3 < nStages) issue((ks + 3) & 3, ks + 3);
    }

#pragma unroll
    for (int mt = 0; mt < 4; mt++) {
        int row0 = m0 + warpM + mt * 16 + g;
        int row1 = row0 + 8;
#pragma unroll
        for (int nt = 0; nt < 4; nt++) {
            int col = n0 + warpN + nt * 8 + tg * 2;
            float bx0 = bi[col], bx1 = bi[col + 1];
            float v0 = acc[mt][nt][0] + bx0;
            float v1 = acc[mt][nt][1] + bx1;
            float v2 = acc[mt][nt][2] + bx0;
            float v3 = acc[mt][nt][3] + bx1;
            if (doElu) {
                v0 = v0 > 0.f ? v0 : expm1f(v0);
                v1 = v1 > 0.f ? v1 : expm1f(v1);
                v2 = v2 > 0.f ? v2 : expm1f(v2);
                v3 = v3 > 0.f ? v3 : expm1f(v3);
            }
            if (row0 < M)
                *(__nv_bfloat162*)(Cb + (size_t)row0 * N + col) =
                    __nv_bfloat162(__float2bfloat16(v0), __float2bfloat16(v1));
            if (row1 < M)
                *(__nv_bfloat162*)(Cb + (size_t)row1 * N + col) =
                    __nv_bfloat162(__float2bfloat16(v2), __float2bfloat16(v3));
        }
    }
}

// ---------------- fused edge kernel: single pass, bf16, data-prefetch -------
// out = (sum_e ex_e * xl[src_e]) / denom ; warp per node, bucket in-edges.
__global__ void __launch_bounds__(256)
edge_fused(const float* __restrict__ We, const float* __restrict__ att,
           const float* __restrict__ bias)
{
    __shared__ float4 sWe[HID / 4];
    __shared__ float4 sAtt[HID / 4];

    for (int i = threadIdx.x; i < HID / 4; i += blockDim.x) {
        sWe[i]  = ((const float4*)We)[i];
        sAtt[i] = ((const float4*)att)[i];
    }
    __syncthreads();

    const int wid  = threadIdx.x >> 5;
    const int lane = threadIdx.x & 31;
    const int node = blockIdx.x * 8 + wid;
    if (node >= NN) return;

    int deg = g_cnt[node];
    if (deg > CAP) deg = CAP;
    const int*   bsrc  = g_bsrc  + (size_t)node * CAP;
    const float* bdist = g_bdist + (size_t)node * CAP;

    // xr[node] slice: 16 channels per lane (bf16 -> fp32 regs)
    float xr[16];
    {
        const uint4* xrp = (const uint4*)(g_xrb + (size_t)node * HID + lane * 16);
        uint4 p0 = xrp[0], p1 = xrp[1];
        const __nv_bfloat162* h0 = (const __nv_bfloat162*)&p0;
        const __nv_bfloat162* h1 = (const __nv_bfloat162*)&p1;
#pragma unroll
        for (int q = 0; q < 4; q++) {
            float2 f0 = __bfloat1622float2(h0[q]);
            float2 f1 = __bfloat1622float2(h1[q]);
            xr[q * 2 + 0] = f0.x; xr[q * 2 + 1] = f0.y;
            xr[8 + q * 2 + 0] = f1.x; xr[8 + q * 2 + 1] = f1.y;
        }
    }
    float we[16], at[16];
#pragma unroll
    for (int q = 0; q < 4; q++) {
        float4 w = sWe[lane * 4 + q], t = sAtt[lane * 4 + q];
        we[q * 4 + 0] = w.x; we[q * 4 + 1] = w.y; we[q * 4 + 2] = w.z; we[q * 4 + 3] = w.w;
        at[q * 4 + 0] = t.x; at[q * 4 + 1] = t.y; at[q * 4 + 2] = t.z; at[q * 4 + 3] = t.w;
    }

    float denom = 0.f;
    float acc[16];
#pragma unroll
    for (int i = 0; i < 16; i++) acc[i] = 0.f;

    // software pipeline: data of edge j+1 in flight while processing edge j
    float dCur = bdist[0];
    uint4 p0c, p1c;
    {
        const uint4* xp = (const uint4*)(g_xlb + (size_t)bsrc[0] * HID + lane * 16);
        p0c = xp[0]; p1c = xp[1];
    }
    for (int j = 0; j < deg; j++) {
        uint4 p0 = p0c, p1 = p1c;
        const float dv = dCur;
        if (j + 1 < deg) {
            int sN = bsrc[j + 1];
            dCur = bdist[j + 1];
            const uint4* xp = (const uint4*)(g_xlb + (size_t)sN * HID + lane * 16);
            p0c = xp[0]; p1c = xp[1];
        }

        float a[16];
        {
            const __nv_bfloat162* h0 = (const __nv_bfloat162*)&p0;
            const __nv_bfloat162* h1 = (const __nv_bfloat162*)&p1;
#pragma unroll
            for (int q = 0; q < 4; q++) {
                float2 f0 = __bfloat1622float2(h0[q]);
                float2 f1 = __bfloat1622float2(h1[q]);
                a[q * 2 + 0] = f0.x; a[q * 2 + 1] = f0.y;
                a[8 + q * 2 + 0] = f1.x; a[8 + q * 2 + 1] = f1.y;
            }
        }

        float partial = 0.f;
#pragma unroll
        for (int i = 0; i < 16; i++) {
            float v = a[i] + xr[i] + dv * we[i];
            v = v > 0.f ? v : 0.2f * v;
            partial += v * at[i];
        }
        partial += __shfl_xor_sync(0xffffffffu, partial, 1);
        partial += __shfl_xor_sync(0xffffffffu, partial, 2);
        float ex = expf(partial);   // softmax shift-invariant; scores O(1)
        denom += ex;
#pragma unroll
        for (int i = 0; i < 16; i++) acc[i] += ex * a[i];
    }

    const float inv = 1.f / denom;      // self-loop => denom > 0

    const float* bp = bias + lane * 16;
    bf16* hbp = g_hb + (size_t)node * HID + lane * 16;
#pragma unroll
    for (int i = 0; i < 16; i += 2) {
        float v0 = acc[i] * inv + bp[i];
        float v1 = acc[i + 1] * inv + bp[i + 1];
        v0 = v0 > 0.f ? v0 : expm1f(v0);
        v1 = v1 > 0.f ? v1 : expm1f(v1);
        *(__nv_bfloat162*)(hbp + i) =
            __nv_bfloat162(__float2bfloat16(v0), __float2bfloat16(v1));
    }
}

// ---------------- final: logits = h @ Wa + ba; log_softmax (h = bf16 hb) ----
__global__ void final_kernel(const float* __restrict__ Wa,
                             const float* __restrict__ ba,
                             float* __restrict__ out)
{
    const int row = blockIdx.x * (blockDim.x >> 5) + (threadIdx.x >> 5);
    const int lane = threadIdx.x & 31;
    if (row >= NN) return;

    const bf16* hrow = g_hb + (size_t)row * HID;
    float acc[NCLS];
#pragma unroll
    for (int c = 0; c < NCLS; c++) acc[c] = 0.f;

    for (int k = lane * 2; k < HID; k += 64) {
        float2 hv = __bfloat1622float2(*(const __nv_bfloat162*)(hrow + k));
        const float* w0 = Wa + (size_t)k * NCLS;
        const float* w1 = w0 + NCLS;
#pragma unroll
        for (int c = 0; c < NCLS; c++) acc[c] += hv.x * w0[c] + hv.y * w1[c];
    }
#pragma unroll
    for (int off = 16; off > 0; off >>= 1)
#pragma unroll
        for (int c = 0; c < NCLS; c++)
            acc[c] += __shfl_xor_sync(0xffffffffu, acc[c], off);

    if (lane == 0) {
        float z[NCLS], mx = -1e30f;
#pragma unroll
        for (int c = 0; c < NCLS; c++) { z[c] = acc[c] + ba[c]; mx = fmaxf(mx, z[c]); }
        float s = 0.f;
#pragma unroll
        for (int c = 0; c < NCLS; c++) s += expf(z[c] - mx);
        float lse = mx + logf(s);
#pragma unroll
        for (int c = 0; c < NCLS; c++) out[(size_t)row * NCLS + c] = z[c] - lse;
    }
}

// ---------------- launch ----------------
extern "C" void kernel_launch(void* const* d_in, const int* in_sizes, int n_in,
                              void* d_out, int out_size)
{
    const float* x    = (const float*)d_in[0];
    const int*   ei   = (const int*)d_in[1];      // int32 (JAX x64 disabled)
    const float* dist = (const float*)d_in[2];
    const float* Wb   = (const float*)d_in[3];
    const float* bb   = (const float*)d_in[4];
    const float* Wl   = (const float*)d_in[5];
    const float* bl   = (const float*)d_in[6];
    const float* Wr   = (const float*)d_in[7];
    const float* br   = (const float*)d_in[8];
    const float* We   = (const float*)d_in[9];
    const float* att  = (const float*)d_in[10];
    const float* bc   = (const float*)d_in[11];
    const float* Wa   = (const float*)d_in[12];
    const float* ba   = (const float*)d_in[13];
    float* out = (float*)d_out;

    bf16 *phb, *pxb, *pxlb, *pxrb, *pwbT, *pwlT, *pwrT;
    cudaGetSymbolAddress((void**)&phb,  g_hb);
    cudaGetSymbolAddress((void**)&pxb,  g_xb);
    cudaGetSymbolAddress((void**)&pxlb, g_xlb);
    cudaGetSymbolAddress((void**)&pxrb, g_xrb);
    cudaGetSymbolAddress((void**)&pwbT, g_wbT);
    cudaGetSymbolAddress((void**)&pwlT, g_wlT);
    cudaGetSymbolAddress((void**)&pwrT, g_wrT);

    cudaFuncSetAttribute(bf16gemm, cudaFuncAttributeMaxDynamicSharedMemorySize, GEMM_SMEM);

    // ---- prep (fcnn GEMM at launch #4 for ncu capture) ----
    conv_x_zero<<<(NN * FIN + 255) / 256, 256>>>(x);                        // 1
    transp_bf16_batch7<<<dim3(HID / 32, HID / 32, 7), dim3(32, 8)>>>(Wl, Wr, Wb); // 2
    bucket_kernel<<<(ETOT + 255) / 256, 256>>>(ei, dist);                   // 3
    // fcnn_before: hb = bf16(elu(x @ Wb + bb))                              // 4
    bf16gemm<<<dim3(HID / 128, (NN + 127) / 128), 256, GEMM_SMEM>>>(
        pxb, pwbT, nullptr, bb, nullptr, phb, nullptr, NN, FIN, 1);

    for (int i = 0; i < 3; i++) {
        // fused dual GEMM: xlb = hb @ Wl^T + bl ; xrb = hb @ Wr^T + br (bf16)
        bf16gemm<<<dim3(2 * HID / 128, (NN + 127) / 128), 256, GEMM_SMEM>>>(
            phb, pwlT + (size_t)i * HID * HID, pwrT + (size_t)i * HID * HID,
            bl + i * HID, br + i * HID, pxlb, pxrb, NN, HID, 0);
        edge_fused<<<(NN + 7) / 8, 256>>>(We + (size_t)i * HID,
                                          att + (size_t)i * HID,
                                          bc + (size_t)i * HID);
    }

    final_kernel<<<(NN + 7) / 8, 256>>>(Wa, ba, out);
}